// round 1
// baseline (speedup 1.0000x reference)
#include <cuda_runtime.h>
#include <cuda_bf16.h>
#include <math.h>

// ---------------- model constants ----------------
#define BV   32000
#define DD   1024
#define DFF  4096
#define LT   2
#define HT   16
#define CC   4
#define DC   256
#define DFFC 1024
#define LC   4
#define HC   4
#define BB   2
#define TT   1024
#define BT   (BB*TT)     // 2048
#define CBT  (CC*BT)     // 8192

// ---------------- scratch (device globals; no allocation) ----------------
__device__ float g_X [BT*DD];
__device__ float g_H [BT*DD];
__device__ float g_Q [BT*DD];
__device__ float g_K [BT*DD];
__device__ float g_V [BT*DD];
__device__ float g_O [BT*DD];
__device__ float g_M1[BT*DFF];
__device__ float g_CS[CC*BT*DC];

// ---------------- SGEMM: C = A@B (+bias) (+C), optional B^T, batched ----------------
#define GBM 128
#define GBN 64
#define GBK 16

__global__ void __launch_bounds__(256) sgemm_kernel(
    const float* __restrict__ A, const float* __restrict__ B,
    const float* __restrict__ bias, float* __restrict__ C,
    int M, int N, int K, int transB, int accum,
    long aBS, long bBS, long cBS, long biasBS)
{
    __shared__ float As[GBK][GBM];
    __shared__ float Bs[GBK][GBN + 4];
    A += (long)blockIdx.z * aBS;
    B += (long)blockIdx.z * bBS;
    C += (long)blockIdx.z * cBS;
    int row0 = blockIdx.y * GBM;
    int col0 = blockIdx.x * GBN;
    int tid  = threadIdx.x;
    int trow = (tid >> 4) << 3;
    int tcol = (tid & 15) << 2;

    float acc[8][4];
#pragma unroll
    for (int i = 0; i < 8; i++)
#pragma unroll
        for (int j = 0; j < 4; j++) acc[i][j] = 0.f;

    for (int k0 = 0; k0 < K; k0 += GBK) {
#pragma unroll
        for (int q = 0; q < 2; q++) {
            int f  = tid * 2 + q;
            int r  = f >> 2;
            int kk = (f & 3) << 2;
            float4 v = *(const float4*)(A + (long)(row0 + r) * K + k0 + kk);
            As[kk + 0][r] = v.x; As[kk + 1][r] = v.y;
            As[kk + 2][r] = v.z; As[kk + 3][r] = v.w;
        }
        if (!transB) {
            int i = tid >> 4;
            int j = (tid & 15) << 2;
            float4 v = *(const float4*)(B + (long)(k0 + i) * N + col0 + j);
            *(float4*)&Bs[i][j] = v;
        } else {
            int n  = tid >> 2;
            int kk = (tid & 3) << 2;
            float4 v = *(const float4*)(B + (long)(col0 + n) * K + k0 + kk);
            Bs[kk + 0][n] = v.x; Bs[kk + 1][n] = v.y;
            Bs[kk + 2][n] = v.z; Bs[kk + 3][n] = v.w;
        }
        __syncthreads();
#pragma unroll
        for (int kk = 0; kk < GBK; kk++) {
            float a[8], b[4];
            *(float4*)&a[0] = *(const float4*)&As[kk][trow];
            *(float4*)&a[4] = *(const float4*)&As[kk][trow + 4];
            *(float4*)&b[0] = *(const float4*)&Bs[kk][tcol];
#pragma unroll
            for (int i = 0; i < 8; i++)
#pragma unroll
                for (int j = 0; j < 4; j++)
                    acc[i][j] = fmaf(a[i], b[j], acc[i][j]);
        }
        __syncthreads();
    }

    float bv[4] = {0.f, 0.f, 0.f, 0.f};
    if (bias) {
        float4 t = *(const float4*)(bias + (long)blockIdx.z * biasBS + col0 + tcol);
        bv[0] = t.x; bv[1] = t.y; bv[2] = t.z; bv[3] = t.w;
    }
#pragma unroll
    for (int i = 0; i < 8; i++) {
        long off = (long)(row0 + trow + i) * N + col0 + tcol;
        float4 r;
        r.x = acc[i][0] + bv[0]; r.y = acc[i][1] + bv[1];
        r.z = acc[i][2] + bv[2]; r.w = acc[i][3] + bv[3];
        if (accum) {
            float4 p = *(const float4*)(C + off);
            r.x += p.x; r.y += p.y; r.z += p.z; r.w += p.w;
        }
        *(float4*)(C + off) = r;
    }
}

// ---------------- flash attention (causal), 64x64 tiles, hd=64 ----------------
#define ATTN_SMEM ((64*64 + 64*65 + 64*64) * 4)

__global__ void __launch_bounds__(256) attn_kernel(
    const float* __restrict__ Qg, const float* __restrict__ Kg,
    const float* __restrict__ Vg, float* __restrict__ Og,
    int T, int nh, int rstride, long colstride)
{
    extern __shared__ float sm[];
    float* Qs = sm;                   // [64][64]
    float* Ks = sm + 64 * 64;         // [64][65] (also reused for P)
    float* Vs = sm + 64 * 64 + 64 * 65; // [64][64]

    int qt = blockIdx.x;
    int b  = blockIdx.y / nh;
    int h  = blockIdx.y % nh;
    long base = (long)blockIdx.z * colstride + (long)h * 64;
    int q0  = qt * 64;
    int tid = threadIdx.x;
    int tx  = tid & 15;
    int trow = ((tid >> 4) << 2);
    int tcol = tx << 2;

    {   // load Q tile
        int r  = tid >> 2;
        int cb = (tid & 3) * 16;
        const float* src = Qg + base + (long)(b * T + q0 + r) * rstride + cb;
#pragma unroll
        for (int j = 0; j < 4; j++) {
            float4 v = *(const float4*)(src + j * 4);
            Qs[r * 64 + cb + j * 4 + 0] = v.x;
            Qs[r * 64 + cb + j * 4 + 1] = v.y;
            Qs[r * 64 + cb + j * 4 + 2] = v.z;
            Qs[r * 64 + cb + j * 4 + 3] = v.w;
        }
    }

    float m[4], l[4], o[4][4];
#pragma unroll
    for (int i = 0; i < 4; i++) {
        m[i] = -1e30f; l[i] = 0.f;
#pragma unroll
        for (int j = 0; j < 4; j++) o[i][j] = 0.f;
    }

    for (int kt = 0; kt <= qt; kt++) {
        int k0 = kt * 64;
        {   // load K,V tiles
            int r  = tid >> 2;
            int cb = (tid & 3) * 16;
            const float* ks = Kg + base + (long)(b * T + k0 + r) * rstride + cb;
            const float* vs = Vg + base + (long)(b * T + k0 + r) * rstride + cb;
#pragma unroll
            for (int j = 0; j < 4; j++) {
                float4 kv = *(const float4*)(ks + j * 4);
                Ks[r * 65 + cb + j * 4 + 0] = kv.x;
                Ks[r * 65 + cb + j * 4 + 1] = kv.y;
                Ks[r * 65 + cb + j * 4 + 2] = kv.z;
                Ks[r * 65 + cb + j * 4 + 3] = kv.w;
                float4 vv = *(const float4*)(vs + j * 4);
                Vs[r * 64 + cb + j * 4 + 0] = vv.x;
                Vs[r * 64 + cb + j * 4 + 1] = vv.y;
                Vs[r * 64 + cb + j * 4 + 2] = vv.z;
                Vs[r * 64 + cb + j * 4 + 3] = vv.w;
            }
        }
        __syncthreads();

        float s[4][4];
#pragma unroll
        for (int i = 0; i < 4; i++)
#pragma unroll
            for (int j = 0; j < 4; j++) s[i][j] = 0.f;

#pragma unroll 8
        for (int kk = 0; kk < 64; kk++) {
            float a0 = Qs[(trow + 0) * 64 + kk];
            float a1 = Qs[(trow + 1) * 64 + kk];
            float a2 = Qs[(trow + 2) * 64 + kk];
            float a3 = Qs[(trow + 3) * 64 + kk];
            float b0 = Ks[(tcol + 0) * 65 + kk];
            float b1 = Ks[(tcol + 1) * 65 + kk];
            float b2 = Ks[(tcol + 2) * 65 + kk];
            float b3 = Ks[(tcol + 3) * 65 + kk];
            s[0][0] = fmaf(a0, b0, s[0][0]); s[0][1] = fmaf(a0, b1, s[0][1]);
            s[0][2] = fmaf(a0, b2, s[0][2]); s[0][3] = fmaf(a0, b3, s[0][3]);
            s[1][0] = fmaf(a1, b0, s[1][0]); s[1][1] = fmaf(a1, b1, s[1][1]);
            s[1][2] = fmaf(a1, b2, s[1][2]); s[1][3] = fmaf(a1, b3, s[1][3]);
            s[2][0] = fmaf(a2, b0, s[2][0]); s[2][1] = fmaf(a2, b1, s[2][1]);
            s[2][2] = fmaf(a2, b2, s[2][2]); s[2][3] = fmaf(a2, b3, s[2][3]);
            s[3][0] = fmaf(a3, b0, s[3][0]); s[3][1] = fmaf(a3, b1, s[3][1]);
            s[3][2] = fmaf(a3, b2, s[3][2]); s[3][3] = fmaf(a3, b3, s[3][3]);
        }

#pragma unroll
        for (int i = 0; i < 4; i++)
#pragma unroll
            for (int j = 0; j < 4; j++) {
                s[i][j] *= 0.125f;
                if (kt == qt && (k0 + tcol + j) > (q0 + trow + i)) s[i][j] = -1e30f;
            }

        float p[4][4];
#pragma unroll
        for (int i = 0; i < 4; i++) {
            float rmax = fmaxf(fmaxf(s[i][0], s[i][1]), fmaxf(s[i][2], s[i][3]));
#pragma unroll
            for (int off = 8; off > 0; off >>= 1)
                rmax = fmaxf(rmax, __shfl_xor_sync(0xffffffffu, rmax, off));
            float mnew  = fmaxf(m[i], rmax);
            float alpha = __expf(m[i] - mnew);
            float rsum = 0.f;
#pragma unroll
            for (int j = 0; j < 4; j++) {
                p[i][j] = __expf(s[i][j] - mnew);
                rsum += p[i][j];
            }
#pragma unroll
            for (int off = 8; off > 0; off >>= 1)
                rsum += __shfl_xor_sync(0xffffffffu, rsum, off);
            l[i] = l[i] * alpha + rsum;
#pragma unroll
            for (int j = 0; j < 4; j++) o[i][j] *= alpha;
            m[i] = mnew;
        }

        __syncthreads();   // everyone done reading Ks
#pragma unroll
        for (int i = 0; i < 4; i++)
#pragma unroll
            for (int j = 0; j < 4; j++)
                Ks[(trow + i) * 65 + tcol + j] = p[i][j];
        __syncthreads();

#pragma unroll 8
        for (int kk = 0; kk < 64; kk++) {
            float a0 = Ks[(trow + 0) * 65 + kk];
            float a1 = Ks[(trow + 1) * 65 + kk];
            float a2 = Ks[(trow + 2) * 65 + kk];
            float a3 = Ks[(trow + 3) * 65 + kk];
            float b0 = Vs[kk * 64 + tcol + 0];
            float b1 = Vs[kk * 64 + tcol + 1];
            float b2 = Vs[kk * 64 + tcol + 2];
            float b3 = Vs[kk * 64 + tcol + 3];
            o[0][0] = fmaf(a0, b0, o[0][0]); o[0][1] = fmaf(a0, b1, o[0][1]);
            o[0][2] = fmaf(a0, b2, o[0][2]); o[0][3] = fmaf(a0, b3, o[0][3]);
            o[1][0] = fmaf(a1, b0, o[1][0]); o[1][1] = fmaf(a1, b1, o[1][1]);
            o[1][2] = fmaf(a1, b2, o[1][2]); o[1][3] = fmaf(a1, b3, o[1][3]);
            o[2][0] = fmaf(a2, b0, o[2][0]); o[2][1] = fmaf(a2, b1, o[2][1]);
            o[2][2] = fmaf(a2, b2, o[2][2]); o[2][3] = fmaf(a2, b3, o[2][3]);
            o[3][0] = fmaf(a3, b0, o[3][0]); o[3][1] = fmaf(a3, b1, o[3][1]);
            o[3][2] = fmaf(a3, b2, o[3][2]); o[3][3] = fmaf(a3, b3, o[3][3]);
        }
        __syncthreads();   // before next tile overwrites Ks/Vs
    }

#pragma unroll
    for (int i = 0; i < 4; i++) {
        float inv = 1.f / l[i];
        float* dst = Og + base + (long)(b * T + q0 + trow + i) * rstride + tcol;
        float4 r;
        r.x = o[i][0] * inv; r.y = o[i][1] * inv;
        r.z = o[i][2] * inv; r.w = o[i][3] * inv;
        *(float4*)dst = r;
    }
}

// ---------------- rmsnorm ----------------
__global__ void rms_kernel(const float* __restrict__ x, const float* __restrict__ w,
                           float* __restrict__ out, int W, int rowsPerChunk, long wStride)
{
    int row = blockIdx.x;
    const float* xr = x + (long)row * W;
    const float* wr = w + (long)(row / rowsPerChunk) * wStride;
    float ss = 0.f;
    for (int i = threadIdx.x; i < W; i += 256) {
        float v = xr[i];
        ss += v * v;
    }
    __shared__ float red[8];
#pragma unroll
    for (int off = 16; off > 0; off >>= 1)
        ss += __shfl_xor_sync(0xffffffffu, ss, off);
    if ((threadIdx.x & 31) == 0) red[threadIdx.x >> 5] = ss;
    __syncthreads();
    float tot = red[0] + red[1] + red[2] + red[3] + red[4] + red[5] + red[6] + red[7];
    float inv = rsqrtf(tot / (float)W + 1e-6f);
    float* outr = out + (long)row * W;
    for (int i = threadIdx.x; i < W; i += 256)
        outr[i] = xr[i] * inv * wr[i];
}

// ---------------- rope (in-place on q and k) ----------------
__global__ void rope_kernel(float* __restrict__ q, float* __restrict__ k,
                            int T, int nh, int rstride, int nrows)
{
    int idx = blockIdx.x * blockDim.x + threadIdx.x;
    if (idx >= nrows * nh * 32) return;
    int i   = idx & 31;
    int h   = (idx >> 5) % nh;
    int row = idx / (32 * nh);
    int t   = row % T;
    float inv = __expf(-(float)(2 * i) * (1.f / 64.f) * 9.210340371976184f); // ln(10000)
    float f = (float)t * inv;
    float s, c;
    sincosf(f, &s, &c);
    long bo = (long)row * rstride + h * 64 + i;
    float q1 = q[bo], q2 = q[bo + 32];
    q[bo]      = q1 * c - q2 * s;
    q[bo + 32] = q2 * c + q1 * s;
    float k1 = k[bo], k2 = k[bo + 32];
    k[bo]      = k1 * c - k2 * s;
    k[bo + 32] = k2 * c + k1 * s;
}

// ---------------- gelu (tanh approx, in-place, vectorized) ----------------
__device__ __forceinline__ float gelu1(float v)
{
    return 0.5f * v * (1.f + tanhf(0.7978845608028654f * (v + 0.044715f * v * v * v)));
}
__global__ void gelu_kernel(float* __restrict__ x, int n4)
{
    int i = blockIdx.x * blockDim.x + threadIdx.x;
    if (i >= n4) return;
    float4 v = ((float4*)x)[i];
    v.x = gelu1(v.x); v.y = gelu1(v.y); v.z = gelu1(v.z); v.w = gelu1(v.w);
    ((float4*)x)[i] = v;
}

// ---------------- embedding gather ----------------
__global__ void embed_kernel(float* __restrict__ X, const float* __restrict__ emb,
                             const int* __restrict__ ids)
{
    int row = blockIdx.x;
    int id  = ids[row];
    const float4* src = (const float4*)(emb + (long)id * DD);
    float4* dst = (float4*)(X + (long)row * DD);
    dst[threadIdx.x] = src[threadIdx.x];
}

// ---------------- cross-column merge attention (C=4, hd=64) ----------------
__global__ void merge_attn_kernel(const float* __restrict__ Qm, const float* __restrict__ Km,
                                  const float* __restrict__ Vm, float* __restrict__ Om)
{
    int gid = blockIdx.x * blockDim.x + threadIdx.x;  // CC*BT*HC = 32768
    int h   = gid & 3;
    int row = (gid >> 2) & (BT - 1);
    int i   = gid >> 13;
    if (i >= CC) return;
    long base  = (long)row * DC + h * 64;
    long cstep = (long)BT * DC;

    float4 q[16];
    const float4* qp = (const float4*)(Qm + i * cstep + base);
#pragma unroll
    for (int t = 0; t < 16; t++) q[t] = qp[t];

    float s[CC];
#pragma unroll
    for (int j = 0; j < CC; j++) {
        const float4* kp = (const float4*)(Km + j * cstep + base);
        float acc = 0.f;
#pragma unroll
        for (int t = 0; t < 16; t++) {
            float4 kv = kp[t];
            acc += q[t].x * kv.x + q[t].y * kv.y + q[t].z * kv.z + q[t].w * kv.w;
        }
        s[j] = acc * 0.125f;
    }
    float mm = fmaxf(fmaxf(s[0], s[1]), fmaxf(s[2], s[3]));
    float a[CC], sum = 0.f;
#pragma unroll
    for (int j = 0; j < CC; j++) { a[j] = __expf(s[j] - mm); sum += a[j]; }
    float isum = 1.f / sum;
#pragma unroll
    for (int j = 0; j < CC; j++) a[j] *= isum;

    float4 o[16];
#pragma unroll
    for (int t = 0; t < 16; t++) { o[t].x = 0.f; o[t].y = 0.f; o[t].z = 0.f; o[t].w = 0.f; }
#pragma unroll
    for (int j = 0; j < CC; j++) {
        const float4* vp = (const float4*)(Vm + j * cstep + base);
        float aj = a[j];
#pragma unroll
        for (int t = 0; t < 16; t++) {
            float4 vv = vp[t];
            o[t].x = fmaf(aj, vv.x, o[t].x);
            o[t].y = fmaf(aj, vv.y, o[t].y);
            o[t].z = fmaf(aj, vv.z, o[t].z);
            o[t].w = fmaf(aj, vv.w, o[t].w);
        }
    }
    float4* op = (float4*)(Om + i * cstep + base);
#pragma unroll
    for (int t = 0; t < 16; t++) op[t] = o[t];
}

// ---------------- (C,B,T,DC) -> (B,T,C*DC) concat ----------------
__global__ void comb_kernel(const float* __restrict__ cs, float* __restrict__ comb)
{
    int gid = blockIdx.x * blockDim.x + threadIdx.x;   // BT*DD/4
    int d4  = gid & (DD / 4 - 1);
    int row = gid / (DD / 4);
    int d = d4 * 4;
    int c = d >> 8;
    int e = d & 255;
    ((float4*)comb)[gid] = *(const float4*)(cs + (long)c * BT * DC + (long)row * DC + e);
}

// ---------------- host-side helpers ----------------
static inline void gemm(const float* A, const float* Bm, float* Cm,
                        int M, int N, int K, int transB, int accum,
                        const float* bias, int batch,
                        long aBS, long bBS, long cBS, long biasBS)
{
    dim3 grid(N / GBN, M / GBM, batch);
    sgemm_kernel<<<grid, 256>>>(A, Bm, bias, Cm, M, N, K, transB, accum, aBS, bBS, cBS, biasBS);
}

extern "C" void kernel_launch(void* const* d_in, const int* in_sizes, int n_in,
                              void* d_out, int out_size)
{
    const int*   ids   = (const int*)d_in[0];
    const float* emb   = (const float*)d_in[1];
    const float* t_wq  = (const float*)d_in[2];
    const float* t_wk  = (const float*)d_in[3];
    const float* t_wv  = (const float*)d_in[4];
    const float* t_wo  = (const float*)d_in[5];
    const float* t_w1  = (const float*)d_in[6];
    const float* t_w2  = (const float*)d_in[7];
    const float* t_n1  = (const float*)d_in[8];
    const float* t_n2  = (const float*)d_in[9];
    const float* cin_w = (const float*)d_in[10];
    const float* cin_b = (const float*)d_in[11];
    const float* c_wq  = (const float*)d_in[12];
    const float* c_wk  = (const float*)d_in[13];
    const float* c_wv  = (const float*)d_in[14];
    const float* c_wo  = (const float*)d_in[15];
    const float* c_w1  = (const float*)d_in[16];
    const float* c_w2  = (const float*)d_in[17];
    const float* c_n1  = (const float*)d_in[18];
    const float* c_n2  = (const float*)d_in[19];
    const float* m_wq  = (const float*)d_in[20];
    const float* m_wk  = (const float*)d_in[21];
    const float* m_wv  = (const float*)d_in[22];
    const float* m_wo  = (const float*)d_in[23];
    const float* m_n   = (const float*)d_in[24];
    const float* oproj = (const float*)d_in[25];
    const float* fnorm = (const float*)d_in[26];
    float* out = (float*)d_out;

    void* p;
    cudaGetSymbolAddress(&p, g_X);  float* X  = (float*)p;
    cudaGetSymbolAddress(&p, g_H);  float* H  = (float*)p;
    cudaGetSymbolAddress(&p, g_Q);  float* Q  = (float*)p;
    cudaGetSymbolAddress(&p, g_K);  float* Kb = (float*)p;
    cudaGetSymbolAddress(&p, g_V);  float* Vb = (float*)p;
    cudaGetSymbolAddress(&p, g_O);  float* O  = (float*)p;
    cudaGetSymbolAddress(&p, g_M1); float* M1 = (float*)p;
    cudaGetSymbolAddress(&p, g_CS); float* CS = (float*)p;

    cudaFuncSetAttribute(attn_kernel, cudaFuncAttributeMaxDynamicSharedMemorySize, ATTN_SMEM);

    embed_kernel<<<BT, 256>>>(X, emb, ids);

    // ---- trunk ----
    for (int l = 0; l < LT; l++) {
        rms_kernel<<<BT, 256>>>(X, t_n1 + (long)l * DD, H, DD, BT, 0);
        gemm(H, t_wq + (long)l * DD * DD, Q,  BT, DD, DD, 0, 0, nullptr, 1, 0, 0, 0, 0);
        gemm(H, t_wk + (long)l * DD * DD, Kb, BT, DD, DD, 0, 0, nullptr, 1, 0, 0, 0, 0);
        gemm(H, t_wv + (long)l * DD * DD, Vb, BT, DD, DD, 0, 0, nullptr, 1, 0, 0, 0, 0);
        rope_kernel<<<(BT * HT * 32) / 256, 256>>>(Q, Kb, TT, HT, DD, BT);
        attn_kernel<<<dim3(TT / 64, BB * HT, 1), 256, ATTN_SMEM>>>(Q, Kb, Vb, O, TT, HT, DD, 0);
        gemm(O, t_wo + (long)l * DD * DD, X, BT, DD, DD, 0, 1, nullptr, 1, 0, 0, 0, 0);
        rms_kernel<<<BT, 256>>>(X, t_n2 + (long)l * DD, H, DD, BT, 0);
        gemm(H, t_w1 + (long)l * DD * DFF, M1, BT, DFF, DD, 0, 0, nullptr, 1, 0, 0, 0, 0);
        gelu_kernel<<<(BT * DFF / 4) / 256, 256>>>(M1, BT * DFF / 4);
        gemm(M1, t_w2 + (long)l * DFF * DD, X, BT, DD, DFF, 0, 1, nullptr, 1, 0, 0, 0, 0);
    }

    // ---- column projection (batched over C, with bias) ----
    gemm(X, cin_w, CS, BT, DC, DD, 0, 0, cin_b, CC, 0, (long)DD * DC, (long)BT * DC, DC);

    // ---- column layers ----
    for (int l = 0; l < LC; l++) {
        rms_kernel<<<CBT, 256>>>(CS, c_n1 + (long)l * DC, H, DC, BT, (long)LC * DC);
        gemm(H, c_wq + (long)l * DC * DC, Q,  BT, DC, DC, 0, 0, nullptr, CC,
             (long)BT * DC, (long)LC * DC * DC, (long)BT * DC, 0);
        gemm(H, c_wk + (long)l * DC * DC, Kb, BT, DC, DC, 0, 0, nullptr, CC,
             (long)BT * DC, (long)LC * DC * DC, (long)BT * DC, 0);
        gemm(H, c_wv + (long)l * DC * DC, Vb, BT, DC, DC, 0, 0, nullptr, CC,
             (long)BT * DC, (long)LC * DC * DC, (long)BT * DC, 0);
        rope_kernel<<<(CBT * HC * 32) / 256, 256>>>(Q, Kb, TT, HC, DC, CBT);
        attn_kernel<<<dim3(TT / 64, BB * HC, CC), 256, ATTN_SMEM>>>(Q, Kb, Vb, O, TT, HC, DC, (long)BT * DC);
        gemm(O, c_wo + (long)l * DC * DC, CS, BT, DC, DC, 0, 1, nullptr, CC,
             (long)BT * DC, (long)LC * DC * DC, (long)BT * DC, 0);
        rms_kernel<<<CBT, 256>>>(CS, c_n2 + (long)l * DC, H, DC, BT, (long)LC * DC);
        gemm(H, c_w1 + (long)l * DC * DFFC, M1, BT, DFFC, DC, 0, 0, nullptr, CC,
             (long)BT * DC, (long)LC * DC * DFFC, (long)BT * DFFC, 0);
        gelu_kernel<<<(CBT * DFFC / 4) / 256, 256>>>(M1, CBT * DFFC / 4);
        gemm(M1, c_w2 + (long)l * DFFC * DC, CS, BT, DC, DFFC, 0, 1, nullptr, CC,
             (long)BT * DFFC, (long)LC * DFFC * DC, (long)BT * DC, 0);

        if (((l + 1) & 1) == 0) {
            int m = (l + 1) / 2 - 1;
            rms_kernel<<<CBT, 256>>>(CS, m_n + (long)m * DC, H, DC, CBT, 0);
            gemm(H, m_wq + (long)m * DC * DC, Q,  CBT, DC, DC, 0, 0, nullptr, 1, 0, 0, 0, 0);
            gemm(H, m_wk + (long)m * DC * DC, Kb, CBT, DC, DC, 0, 0, nullptr, 1, 0, 0, 0, 0);
            gemm(H, m_wv + (long)m * DC * DC, Vb, CBT, DC, DC, 0, 0, nullptr, 1, 0, 0, 0, 0);
            merge_attn_kernel<<<(CC * BT * HC) / 256, 256>>>(Q, Kb, Vb, O);
            gemm(O, m_wo + (long)m * DC * DC, CS, CBT, DC, DC, 0, 1, nullptr, 1, 0, 0, 0, 0);
        }
    }

    // ---- output head ----
    comb_kernel<<<(BT * DD / 4) / 256, 256>>>(CS, H);
    gemm(H, oproj, Q, BT, DD, DD, 0, 0, nullptr, 1, 0, 0, 0, 0);
    rms_kernel<<<BT, 256>>>(Q, fnorm, H, DD, BT, 0);
    gemm(H, emb, out, BT, BV, DD, 1, 0, nullptr, 1, 0, 0, 0, 0);
}

// round 2
// speedup vs baseline: 1.9516x; 1.9516x over previous
#include <cuda_runtime.h>
#include <cuda_fp16.h>
#include <math.h>
#include <stdint.h>

// ---------------- model constants ----------------
#define BV   32000
#define DD   1024
#define DFF  4096
#define LT   2
#define HT   16
#define CC   4
#define DC   256
#define DFFC 1024
#define LC   4
#define HC   4
#define NM   2
#define BB   2
#define TT   1024
#define BT   (BB*TT)     // 2048
#define CBT  (CC*BT)     // 8192

// ---------------- weight offsets (transposed [N][K] fp16 store) ----------------
constexpr long OT_WQ = 0;
constexpr long OT_WK = OT_WQ + (long)LT*DD*DD;
constexpr long OT_WV = OT_WK + (long)LT*DD*DD;
constexpr long OT_WO = OT_WV + (long)LT*DD*DD;
constexpr long OT_W1 = OT_WO + (long)LT*DD*DD;
constexpr long OT_W2 = OT_W1 + (long)LT*DD*DFF;
constexpr long OC_IN = OT_W2 + (long)LT*DFF*DD;
constexpr long OC_WQ = OC_IN + (long)CC*DD*DC;
constexpr long OC_WK = OC_WQ + (long)CC*LC*DC*DC;
constexpr long OC_WV = OC_WK + (long)CC*LC*DC*DC;
constexpr long OC_WO = OC_WV + (long)CC*LC*DC*DC;
constexpr long OC_W1 = OC_WO + (long)CC*LC*DC*DC;
constexpr long OC_W2 = OC_W1 + (long)CC*LC*DC*DFFC;
constexpr long OM_WQ = OC_W2 + (long)CC*LC*DFFC*DC;
constexpr long OM_WK = OM_WQ + (long)NM*DC*DC;
constexpr long OM_WV = OM_WK + (long)NM*DC*DC;
constexpr long OM_WO = OM_WV + (long)NM*DC*DC;
constexpr long O_OP  = OM_WO + (long)NM*DC*DC;
constexpr long O_EMB = O_OP  + (long)DD*DD;
constexpr long WTOT  = O_EMB + (long)BV*DD;

// ---------------- scratch (device globals) ----------------
__device__ float  g_X [BT*DD];
__device__ float  g_Q [BT*DD];
__device__ float  g_K [BT*DD];
__device__ float  g_V [BT*DD];
__device__ float  g_M1[BT*DFF];
__device__ float  g_CS[CC*BT*DC];
__device__ __half g_Hh[BT*DD];
__device__ __half g_Hl[BT*DD];
__device__ __half g_M1h[BT*DFF];
__device__ __half g_M1l[BT*DFF];
__device__ __half g_Oh[BT*DD];
__device__ __half g_Ol[BT*DD];
__device__ __half g_Wh[WTOT];
__device__ __half g_Wl[WTOT];

// ---------------- mma helpers ----------------
__device__ __forceinline__ void lm4(const __half* p, uint32_t* r)
{
    uint32_t a = (uint32_t)__cvta_generic_to_shared(p);
    asm volatile("ldmatrix.sync.aligned.m8n8.x4.shared.b16 {%0,%1,%2,%3}, [%4];"
        : "=r"(r[0]), "=r"(r[1]), "=r"(r[2]), "=r"(r[3]) : "r"(a));
}
__device__ __forceinline__ void mma16816(float* c, const uint32_t* a, const uint32_t* b)
{
    asm volatile("mma.sync.aligned.m16n8k16.row.col.f32.f16.f16.f32 "
        "{%0,%1,%2,%3},{%4,%5,%6,%7},{%8,%9},{%0,%1,%2,%3};"
        : "+f"(c[0]), "+f"(c[1]), "+f"(c[2]), "+f"(c[3])
        : "r"(a[0]), "r"(a[1]), "r"(a[2]), "r"(a[3]), "r"(b[0]), "r"(b[1]));
}

// ---------------- HGEMM: C(fp32) = A(f16 hi/lo) @ B(f16 hi/lo)^T-layout ----------------
// A: [M][K] row-major, B: [N][K] row-major (both K-contiguous), C: [M][N] fp32.
// NT=2: 2-term split (hi*hi + hi*lo + lo*hi) -> ~fp32 accuracy. NT=1: plain fp16.
#define BM 128
#define BN 128
#define BKH 32
#define SSTR 40

template<int NT>
__global__ void __launch_bounds__(256) hgemm_kernel(
    const __half* __restrict__ Ah, const __half* __restrict__ Al,
    const __half* __restrict__ Bh, const __half* __restrict__ Bl,
    const float* __restrict__ bias, float* __restrict__ C,
    int M, int N, int K, int accum,
    long aBS, long bBS, long cBS, long biasBS)
{
    __shared__ __half sAh[BM*SSTR];
    __shared__ __half sBh[BN*SSTR];
    __shared__ __half sAl[NT == 2 ? BM*SSTR : 8];
    __shared__ __half sBl[NT == 2 ? BN*SSTR : 8];

    Ah += blockIdx.z * aBS;
    Bh += blockIdx.z * bBS;
    C  += blockIdx.z * cBS;
    if (NT == 2) { Al += blockIdx.z * aBS; Bl += blockIdx.z * bBS; }
    if (bias) bias += blockIdx.z * biasBS;

    int row0 = blockIdx.y * BM;
    int col0 = blockIdx.x * BN;
    int tid  = threadIdx.x;
    int lane = tid & 31;
    int wid  = tid >> 5;
    int wm0  = (wid >> 2) * 64;
    int wn0  = (wid & 3) * 32;

    float acc[4][4][4];
#pragma unroll
    for (int mt = 0; mt < 4; mt++)
#pragma unroll
        for (int nt = 0; nt < 4; nt++)
#pragma unroll
            for (int q = 0; q < 4; q++) acc[mt][nt][q] = 0.f;

    // ldmatrix address precompute
    int a_r   = lane & 15;
    int a_ko  = (lane >> 4) << 3;
    int b_n   = ((lane >> 4) << 3) + (lane & 7);
    int b_ko  = ((lane >> 3) & 1) << 3;

    for (int k0 = 0; k0 < K; k0 += BKH) {
#pragma unroll
        for (int c = tid; c < 512; c += 256) {
            int r = c >> 2, o = (c & 3) << 3;
            *(uint4*)&sAh[r*SSTR + o] = *(const uint4*)&Ah[(long)(row0 + r)*K + k0 + o];
            *(uint4*)&sBh[r*SSTR + o] = *(const uint4*)&Bh[(long)(col0 + r)*K + k0 + o];
            if (NT == 2) {
                *(uint4*)&sAl[r*SSTR + o] = *(const uint4*)&Al[(long)(row0 + r)*K + k0 + o];
                *(uint4*)&sBl[r*SSTR + o] = *(const uint4*)&Bl[(long)(col0 + r)*K + k0 + o];
            }
        }
        __syncthreads();

#pragma unroll
        for (int ks = 0; ks < BKH; ks += 16) {
            uint32_t a_hi[4][4], b_hi[2][4];
#pragma unroll
            for (int mt = 0; mt < 4; mt++)
                lm4(&sAh[(wm0 + mt*16 + a_r)*SSTR + ks + a_ko], a_hi[mt]);
#pragma unroll
            for (int np = 0; np < 2; np++)
                lm4(&sBh[(wn0 + np*16 + b_n)*SSTR + ks + b_ko], b_hi[np]);
#pragma unroll
            for (int mt = 0; mt < 4; mt++)
#pragma unroll
                for (int nt = 0; nt < 4; nt++)
                    mma16816(acc[mt][nt], a_hi[mt], &b_hi[nt >> 1][(nt & 1)*2]);

            if (NT == 2) {
                uint32_t b_lo[2][4];
#pragma unroll
                for (int np = 0; np < 2; np++)
                    lm4(&sBl[(wn0 + np*16 + b_n)*SSTR + ks + b_ko], b_lo[np]);
#pragma unroll
                for (int mt = 0; mt < 4; mt++)
#pragma unroll
                    for (int nt = 0; nt < 4; nt++)
                        mma16816(acc[mt][nt], a_hi[mt], &b_lo[nt >> 1][(nt & 1)*2]);
                uint32_t a_lo[4][4];
#pragma unroll
                for (int mt = 0; mt < 4; mt++)
                    lm4(&sAl[(wm0 + mt*16 + a_r)*SSTR + ks + a_ko], a_lo[mt]);
#pragma unroll
                for (int mt = 0; mt < 4; mt++)
#pragma unroll
                    for (int nt = 0; nt < 4; nt++)
                        mma16816(acc[mt][nt], a_lo[mt], &b_hi[nt >> 1][(nt & 1)*2]);
            }
        }
        __syncthreads();
    }

    int g = lane >> 2, t = lane & 3;
#pragma unroll
    for (int mt = 0; mt < 4; mt++) {
#pragma unroll
        for (int nt = 0; nt < 4; nt++) {
            int r1  = row0 + wm0 + mt*16 + g;
            int cix = col0 + wn0 + nt*8 + 2*t;
            float bv0 = 0.f, bv1 = 0.f;
            if (bias) { bv0 = bias[cix]; bv1 = bias[cix + 1]; }
            float2 v0 = make_float2(acc[mt][nt][0] + bv0, acc[mt][nt][1] + bv1);
            float2 v1 = make_float2(acc[mt][nt][2] + bv0, acc[mt][nt][3] + bv1);
            long o0 = (long)r1*N + cix;
            long o1 = (long)(r1 + 8)*N + cix;
            if (accum) {
                float2 p0 = *(float2*)&C[o0];
                float2 p1 = *(float2*)&C[o1];
                v0.x += p0.x; v0.y += p0.y;
                v1.x += p1.x; v1.y += p1.y;
            }
            *(float2*)&C[o0] = v0;
            *(float2*)&C[o1] = v1;
        }
    }
}

// ---------------- weight transpose + fp16 split: [K][N] fp32 -> [N][K] hi/lo ----------------
__global__ void splitT_kernel(const float* __restrict__ in, __half* __restrict__ oh,
                              __half* __restrict__ ol, int K, int N,
                              long inStride, long outStride)
{
    __shared__ float tile[32][33];
    in += blockIdx.z * inStride;
    long ob = blockIdx.z * outStride;
    int n0 = blockIdx.x * 32, k0 = blockIdx.y * 32;
    int tx = threadIdx.x & 31, ty = threadIdx.x >> 5;
#pragma unroll
    for (int j = 0; j < 4; j++) {
        int r = ty*4 + j;
        tile[r][tx] = in[(long)(k0 + r)*N + n0 + tx];
    }
    __syncthreads();
#pragma unroll
    for (int j = 0; j < 4; j++) {
        int nn = ty*4 + j;
        float v = tile[tx][nn];
        __half h = __float2half(v);
        long o = ob + (long)(n0 + nn)*K + k0 + tx;
        oh[o] = h;
        ol[o] = __float2half(v - __half2float(h));
    }
}

// plain fp32 -> fp16 (hi only), for emb
__global__ void split1_kernel(const float* __restrict__ in, __half* __restrict__ oh, int n4)
{
    int i = blockIdx.x * blockDim.x + threadIdx.x;
    if (i >= n4) return;
    float4 v = ((const float4*)in)[i];
    oh[4*i + 0] = __float2half(v.x);
    oh[4*i + 1] = __float2half(v.y);
    oh[4*i + 2] = __float2half(v.z);
    oh[4*i + 3] = __float2half(v.w);
}

// plain fp32 -> fp16 hi/lo
__device__ __forceinline__ void split_store(__half* oh, __half* ol, int idx, float v)
{
    __half h = __float2half(v);
    oh[idx] = h;
    ol[idx] = __float2half(v - __half2float(h));
}
__global__ void split2_kernel(const float* __restrict__ in, __half* __restrict__ oh,
                              __half* __restrict__ ol, int n4)
{
    int i = blockIdx.x * blockDim.x + threadIdx.x;
    if (i >= n4) return;
    float4 v = ((const float4*)in)[i];
    split_store(oh, ol, 4*i + 0, v.x);
    split_store(oh, ol, 4*i + 1, v.y);
    split_store(oh, ol, 4*i + 2, v.z);
    split_store(oh, ol, 4*i + 3, v.w);
}

// ---------------- flash attention (causal), fp32 math, fp16 hi/lo output ----------------
#define ATTN_SMEM ((64*64 + 64*65 + 64*64) * 4)

__global__ void __launch_bounds__(256) attn_kernel(
    const float* __restrict__ Qg, const float* __restrict__ Kg,
    const float* __restrict__ Vg, __half* __restrict__ Ogh, __half* __restrict__ Ogl,
    int T, int nh, int rstride, long colstride)
{
    extern __shared__ float sm[];
    float* Qs = sm;
    float* Ks = sm + 64*64;
    float* Vs = sm + 64*64 + 64*65;

    int qt = blockIdx.x;
    int b  = blockIdx.y / nh;
    int h  = blockIdx.y % nh;
    long base = (long)blockIdx.z * colstride + (long)h * 64;
    int q0  = qt * 64;
    int tid = threadIdx.x;
    int trow = ((tid >> 4) << 2);
    int tcol = (tid & 15) << 2;

    {
        int r  = tid >> 2;
        int cb = (tid & 3) * 16;
        const float* src = Qg + base + (long)(b*T + q0 + r)*rstride + cb;
#pragma unroll
        for (int j = 0; j < 4; j++) {
            float4 v = *(const float4*)(src + j*4);
            Qs[r*64 + cb + j*4 + 0] = v.x; Qs[r*64 + cb + j*4 + 1] = v.y;
            Qs[r*64 + cb + j*4 + 2] = v.z; Qs[r*64 + cb + j*4 + 3] = v.w;
        }
    }

    float m[4], l[4], o[4][4];
#pragma unroll
    for (int i = 0; i < 4; i++) {
        m[i] = -1e30f; l[i] = 0.f;
#pragma unroll
        for (int j = 0; j < 4; j++) o[i][j] = 0.f;
    }

    for (int kt = 0; kt <= qt; kt++) {
        int k0 = kt * 64;
        {
            int r  = tid >> 2;
            int cb = (tid & 3) * 16;
            const float* ks = Kg + base + (long)(b*T + k0 + r)*rstride + cb;
            const float* vs = Vg + base + (long)(b*T + k0 + r)*rstride + cb;
#pragma unroll
            for (int j = 0; j < 4; j++) {
                float4 kv = *(const float4*)(ks + j*4);
                Ks[r*65 + cb + j*4 + 0] = kv.x; Ks[r*65 + cb + j*4 + 1] = kv.y;
                Ks[r*65 + cb + j*4 + 2] = kv.z; Ks[r*65 + cb + j*4 + 3] = kv.w;
                float4 vv = *(const float4*)(vs + j*4);
                Vs[r*64 + cb + j*4 + 0] = vv.x; Vs[r*64 + cb + j*4 + 1] = vv.y;
                Vs[r*64 + cb + j*4 + 2] = vv.z; Vs[r*64 + cb + j*4 + 3] = vv.w;
            }
        }
        __syncthreads();

        float s[4][4];
#pragma unroll
        for (int i = 0; i < 4; i++)
#pragma unroll
            for (int j = 0; j < 4; j++) s[i][j] = 0.f;

#pragma unroll 8
        for (int kk = 0; kk < 64; kk++) {
            float a0 = Qs[(trow+0)*64 + kk], a1 = Qs[(trow+1)*64 + kk];
            float a2 = Qs[(trow+2)*64 + kk], a3 = Qs[(trow+3)*64 + kk];
            float b0 = Ks[(tcol+0)*65 + kk], b1 = Ks[(tcol+1)*65 + kk];
            float b2 = Ks[(tcol+2)*65 + kk], b3 = Ks[(tcol+3)*65 + kk];
            s[0][0] = fmaf(a0,b0,s[0][0]); s[0][1] = fmaf(a0,b1,s[0][1]);
            s[0][2] = fmaf(a0,b2,s[0][2]); s[0][3] = fmaf(a0,b3,s[0][3]);
            s[1][0] = fmaf(a1,b0,s[1][0]); s[1][1] = fmaf(a1,b1,s[1][1]);
            s[1][2] = fmaf(a1,b2,s[1][2]); s[1][3] = fmaf(a1,b3,s[1][3]);
            s[2][0] = fmaf(a2,b0,s[2][0]); s[2][1] = fmaf(a2,b1,s[2][1]);
            s[2][2] = fmaf(a2,b2,s[2][2]); s[2][3] = fmaf(a2,b3,s[2][3]);
            s[3][0] = fmaf(a3,b0,s[3][0]); s[3][1] = fmaf(a3,b1,s[3][1]);
            s[3][2] = fmaf(a3,b2,s[3][2]); s[3][3] = fmaf(a3,b3,s[3][3]);
        }

#pragma unroll
        for (int i = 0; i < 4; i++)
#pragma unroll
            for (int j = 0; j < 4; j++) {
                s[i][j] *= 0.125f;
                if (kt == qt && (k0 + tcol + j) > (q0 + trow + i)) s[i][j] = -1e30f;
            }

        float p[4][4];
#pragma unroll
        for (int i = 0; i < 4; i++) {
            float rmax = fmaxf(fmaxf(s[i][0], s[i][1]), fmaxf(s[i][2], s[i][3]));
#pragma unroll
            for (int off = 8; off > 0; off >>= 1)
                rmax = fmaxf(rmax, __shfl_xor_sync(0xffffffffu, rmax, off));
            float mnew  = fmaxf(m[i], rmax);
            float alpha = __expf(m[i] - mnew);
            float rsum = 0.f;
#pragma unroll
            for (int j = 0; j < 4; j++) { p[i][j] = __expf(s[i][j] - mnew); rsum += p[i][j]; }
#pragma unroll
            for (int off = 8; off > 0; off >>= 1)
                rsum += __shfl_xor_sync(0xffffffffu, rsum, off);
            l[i] = l[i]*alpha + rsum;
#pragma unroll
            for (int j = 0; j < 4; j++) o[i][j] *= alpha;
            m[i] = mnew;
        }

        __syncthreads();
#pragma unroll
        for (int i = 0; i < 4; i++)
#pragma unroll
            for (int j = 0; j < 4; j++)
                Ks[(trow+i)*65 + tcol + j] = p[i][j];
        __syncthreads();

#pragma unroll 8
        for (int kk = 0; kk < 64; kk++) {
            float a0 = Ks[(trow+0)*65 + kk], a1 = Ks[(trow+1)*65 + kk];
            float a2 = Ks[(trow+2)*65 + kk], a3 = Ks[(trow+3)*65 + kk];
            float b0 = Vs[kk*64 + tcol + 0], b1 = Vs[kk*64 + tcol + 1];
            float b2 = Vs[kk*64 + tcol + 2], b3 = Vs[kk*64 + tcol + 3];
            o[0][0] = fmaf(a0,b0,o[0][0]); o[0][1] = fmaf(a0,b1,o[0][1]);
            o[0][2] = fmaf(a0,b2,o[0][2]); o[0][3] = fmaf(a0,b3,o[0][3]);
            o[1][0] = fmaf(a1,b0,o[1][0]); o[1][1] = fmaf(a1,b1,o[1][1]);
            o[1][2] = fmaf(a1,b2,o[1][2]); o[1][3] = fmaf(a1,b3,o[1][3]);
            o[2][0] = fmaf(a2,b0,o[2][0]); o[2][1] = fmaf(a2,b1,o[2][1]);
            o[2][2] = fmaf(a2,b2,o[2][2]); o[2][3] = fmaf(a2,b3,o[2][3]);
            o[3][0] = fmaf(a3,b0,o[3][0]); o[3][1] = fmaf(a3,b1,o[3][1]);
            o[3][2] = fmaf(a3,b2,o[3][2]); o[3][3] = fmaf(a3,b3,o[3][3]);
        }
        __syncthreads();
    }

#pragma unroll
    for (int i = 0; i < 4; i++) {
        float inv = 1.f / l[i];
        long off = base + (long)(b*T + q0 + trow + i)*rstride + tcol;
#pragma unroll
        for (int j = 0; j < 4; j++) {
            float v = o[i][j] * inv;
            __half h = __float2half(v);
            Ogh[off + j] = h;
            Ogl[off + j] = __float2half(v - __half2float(h));
        }
    }
}

// ---------------- rmsnorm -> fp16 hi/lo ----------------
__global__ void rms_kernel(const float* __restrict__ x, const float* __restrict__ w,
                           __half* __restrict__ oh, __half* __restrict__ ol,
                           int W, int rowsPerChunk, long wStride)
{
    int row = blockIdx.x;
    const float* xr = x + (long)row * W;
    const float* wr = w + (long)(row / rowsPerChunk) * wStride;
    float ss = 0.f;
    for (int i = threadIdx.x; i < W; i += 256) {
        float v = xr[i];
        ss += v * v;
    }
    __shared__ float red[8];
#pragma unroll
    for (int off = 16; off > 0; off >>= 1)
        ss += __shfl_xor_sync(0xffffffffu, ss, off);
    if ((threadIdx.x & 31) == 0) red[threadIdx.x >> 5] = ss;
    __syncthreads();
    float tot = red[0]+red[1]+red[2]+red[3]+red[4]+red[5]+red[6]+red[7];
    float inv = rsqrtf(tot / (float)W + 1e-6f);
    long rb = (long)row * W;
    for (int i = threadIdx.x; i < W; i += 256)
        split_store(oh, ol, rb + i, xr[i] * inv * wr[i]);
}

// ---------------- rope ----------------
__global__ void rope_kernel(float* __restrict__ q, float* __restrict__ k,
                            int T, int nh, int rstride, int nrows)
{
    int idx = blockIdx.x * blockDim.x + threadIdx.x;
    if (idx >= nrows * nh * 32) return;
    int i   = idx & 31;
    int h   = (idx >> 5) % nh;
    int row = idx / (32 * nh);
    int t   = row % T;
    float inv = __expf(-(float)(2*i) * (1.f/64.f) * 9.210340371976184f);
    float f = (float)t * inv;
    float s, c;
    sincosf(f, &s, &c);
    long bo = (long)row * rstride + h*64 + i;
    float q1 = q[bo], q2 = q[bo + 32];
    q[bo] = q1*c - q2*s;  q[bo + 32] = q2*c + q1*s;
    float k1 = k[bo], k2 = k[bo + 32];
    k[bo] = k1*c - k2*s;  k[bo + 32] = k2*c + k1*s;
}

// ---------------- gelu: fp32 in -> fp16 hi/lo ----------------
__device__ __forceinline__ float gelu1(float v)
{
    return 0.5f * v * (1.f + tanhf(0.7978845608028654f * (v + 0.044715f*v*v*v)));
}
__global__ void gelu_kernel(const float* __restrict__ x, __half* __restrict__ oh,
                            __half* __restrict__ ol, int n4)
{
    int i = blockIdx.x * blockDim.x + threadIdx.x;
    if (i >= n4) return;
    float4 v = ((const float4*)x)[i];
    split_store(oh, ol, 4*i + 0, gelu1(v.x));
    split_store(oh, ol, 4*i + 1, gelu1(v.y));
    split_store(oh, ol, 4*i + 2, gelu1(v.z));
    split_store(oh, ol, 4*i + 3, gelu1(v.w));
}

// ---------------- embedding gather ----------------
__global__ void embed_kernel(float* __restrict__ X, const float* __restrict__ emb,
                             const int* __restrict__ ids)
{
    int row = blockIdx.x;
    int id  = ids[row];
    const float4* src = (const float4*)(emb + (long)id * DD);
    float4* dst = (float4*)(X + (long)row * DD);
    dst[threadIdx.x] = src[threadIdx.x];
}

// ---------------- cross-column merge attention ----------------
__global__ void merge_attn_kernel(const float* __restrict__ Qm, const float* __restrict__ Km,
                                  const float* __restrict__ Vm,
                                  __half* __restrict__ Oh, __half* __restrict__ Ol)
{
    int gid = blockIdx.x * blockDim.x + threadIdx.x;
    int h   = gid & 3;
    int row = (gid >> 2) & (BT - 1);
    int i   = gid >> 13;
    if (i >= CC) return;
    long base  = (long)row * DC + h*64;
    long cstep = (long)BT * DC;

    float4 q[16];
    const float4* qp = (const float4*)(Qm + i*cstep + base);
#pragma unroll
    for (int t = 0; t < 16; t++) q[t] = qp[t];

    float s[CC];
#pragma unroll
    for (int j = 0; j < CC; j++) {
        const float4* kp = (const float4*)(Km + j*cstep + base);
        float acc = 0.f;
#pragma unroll
        for (int t = 0; t < 16; t++) {
            float4 kv = kp[t];
            acc += q[t].x*kv.x + q[t].y*kv.y + q[t].z*kv.z + q[t].w*kv.w;
        }
        s[j] = acc * 0.125f;
    }
    float mm = fmaxf(fmaxf(s[0], s[1]), fmaxf(s[2], s[3]));
    float a[CC], sum = 0.f;
#pragma unroll
    for (int j = 0; j < CC; j++) { a[j] = __expf(s[j] - mm); sum += a[j]; }
    float isum = 1.f / sum;
#pragma unroll
    for (int j = 0; j < CC; j++) a[j] *= isum;

    float o[64];
#pragma unroll
    for (int t = 0; t < 64; t++) o[t] = 0.f;
#pragma unroll
    for (int j = 0; j < CC; j++) {
        const float4* vp = (const float4*)(Vm + j*cstep + base);
        float aj = a[j];
#pragma unroll
        for (int t = 0; t < 16; t++) {
            float4 vv = vp[t];
            o[4*t+0] = fmaf(aj, vv.x, o[4*t+0]);
            o[4*t+1] = fmaf(aj, vv.y, o[4*t+1]);
            o[4*t+2] = fmaf(aj, vv.z, o[4*t+2]);
            o[4*t+3] = fmaf(aj, vv.w, o[4*t+3]);
        }
    }
    long ob = i*cstep + base;
#pragma unroll
    for (int t = 0; t < 64; t++) split_store(Oh, Ol, ob + t, o[t]);
}

// ---------------- (C,B,T,DC) -> (B,T,C*DC) concat, fp16 hi/lo out ----------------
__global__ void comb_kernel(const float* __restrict__ cs, __half* __restrict__ oh,
                            __half* __restrict__ ol)
{
    int gid = blockIdx.x * blockDim.x + threadIdx.x;
    int d4  = gid & (DD/4 - 1);
    int row = gid / (DD/4);
    int d = d4 * 4;
    int c = d >> 8;
    int e = d & 255;
    float4 v = *(const float4*)(cs + (long)c*BT*DC + (long)row*DC + e);
    split_store(oh, ol, 4*gid + 0, v.x);
    split_store(oh, ol, 4*gid + 1, v.y);
    split_store(oh, ol, 4*gid + 2, v.z);
    split_store(oh, ol, 4*gid + 3, v.w);
}

// ---------------- host side ----------------
static __half *Wh_p, *Wl_p;

static inline void hgemm(const __half* Ah, const __half* Al, long boff, float* C,
                         int M, int N, int K, int accum, const float* bias, int batch,
                         long aBS, long bBS, long cBS, long biasBS, int nt)
{
    dim3 grid(N/BN, M/BM, batch);
    if (nt == 2)
        hgemm_kernel<2><<<grid, 256>>>(Ah, Al, Wh_p + boff, Wl_p + boff, bias, C,
                                       M, N, K, accum, aBS, bBS, cBS, biasBS);
    else
        hgemm_kernel<1><<<grid, 256>>>(Ah, nullptr, Wh_p + boff, nullptr, bias, C,
                                       M, N, K, accum, aBS, bBS, cBS, biasBS);
}

static inline void splitT(const float* in, long off, int K, int N, int batch)
{
    splitT_kernel<<<dim3(N/32, K/32, batch), 256>>>(in, Wh_p + off, Wl_p + off,
                                                    K, N, (long)K*N, (long)K*N);
}

extern "C" void kernel_launch(void* const* d_in, const int* in_sizes, int n_in,
                              void* d_out, int out_size)
{
    const int*   ids   = (const int*)d_in[0];
    const float* emb   = (const float*)d_in[1];
    const float* t_wq  = (const float*)d_in[2];
    const float* t_wk  = (const float*)d_in[3];
    const float* t_wv  = (const float*)d_in[4];
    const float* t_wo  = (const float*)d_in[5];
    const float* t_w1  = (const float*)d_in[6];
    const float* t_w2  = (const float*)d_in[7];
    const float* t_n1  = (const float*)d_in[8];
    const float* t_n2  = (const float*)d_in[9];
    const float* cin_w = (const float*)d_in[10];
    const float* cin_b = (const float*)d_in[11];
    const float* c_wq  = (const float*)d_in[12];
    const float* c_wk  = (const float*)d_in[13];
    const float* c_wv  = (const float*)d_in[14];
    const float* c_wo  = (const float*)d_in[15];
    const float* c_w1  = (const float*)d_in[16];
    const float* c_w2  = (const float*)d_in[17];
    const float* c_n1  = (const float*)d_in[18];
    const float* c_n2  = (const float*)d_in[19];
    const float* m_wq  = (const float*)d_in[20];
    const float* m_wk  = (const float*)d_in[21];
    const float* m_wv  = (const float*)d_in[22];
    const float* m_wo  = (const float*)d_in[23];
    const float* m_n   = (const float*)d_in[24];
    const float* oproj = (const float*)d_in[25];
    const float* fnorm = (const float*)d_in[26];
    float* out = (float*)d_out;

    void* p;
    cudaGetSymbolAddress(&p, g_X);   float*  X   = (float*)p;
    cudaGetSymbolAddress(&p, g_Q);   float*  Q   = (float*)p;
    cudaGetSymbolAddress(&p, g_K);   float*  Kb  = (float*)p;
    cudaGetSymbolAddress(&p, g_V);   float*  Vb  = (float*)p;
    cudaGetSymbolAddress(&p, g_M1);  float*  M1  = (float*)p;
    cudaGetSymbolAddress(&p, g_CS);  float*  CS  = (float*)p;
    cudaGetSymbolAddress(&p, g_Hh);  __half* Hh  = (__half*)p;
    cudaGetSymbolAddress(&p, g_Hl);  __half* Hl  = (__half*)p;
    cudaGetSymbolAddress(&p, g_M1h); __half* M1h = (__half*)p;
    cudaGetSymbolAddress(&p, g_M1l); __half* M1l = (__half*)p;
    cudaGetSymbolAddress(&p, g_Oh);  __half* Oh  = (__half*)p;
    cudaGetSymbolAddress(&p, g_Ol);  __half* Ol  = (__half*)p;
    cudaGetSymbolAddress(&p, g_Wh);  Wh_p = (__half*)p;
    cudaGetSymbolAddress(&p, g_Wl);  Wl_p = (__half*)p;

    cudaFuncSetAttribute(attn_kernel, cudaFuncAttributeMaxDynamicSharedMemorySize, ATTN_SMEM);

    // ---- weight conversion (transpose + fp16 split) ----
    splitT(t_wq, OT_WQ, DD, DD, LT);
    splitT(t_wk, OT_WK, DD, DD, LT);
    splitT(t_wv, OT_WV, DD, DD, LT);
    splitT(t_wo, OT_WO, DD, DD, LT);
    splitT(t_w1, OT_W1, DD, DFF, LT);
    splitT(t_w2, OT_W2, DFF, DD, LT);
    splitT(cin_w, OC_IN, DD, DC, CC);
    splitT(c_wq, OC_WQ, DC, DC, CC*LC);
    splitT(c_wk, OC_WK, DC, DC, CC*LC);
    splitT(c_wv, OC_WV, DC, DC, CC*LC);
    splitT(c_wo, OC_WO, DC, DC, CC*LC);
    splitT(c_w1, OC_W1, DC, DFFC, CC*LC);
    splitT(c_w2, OC_W2, DFFC, DC, CC*LC);
    splitT(m_wq, OM_WQ, DC, DC, NM);
    splitT(m_wk, OM_WK, DC, DC, NM);
    splitT(m_wv, OM_WV, DC, DC, NM);
    splitT(m_wo, OM_WO, DC, DC, NM);
    splitT(oproj, O_OP, DD, DD, 1);
    split1_kernel<<<(BV*DD/4 + 255)/256, 256>>>(emb, Wh_p + O_EMB, BV*DD/4);

    embed_kernel<<<BT, 256>>>(X, emb, ids);

    // ---- trunk ----
    for (int l = 0; l < LT; l++) {
        rms_kernel<<<BT, 256>>>(X, t_n1 + (long)l*DD, Hh, Hl, DD, BT, 0);
        hgemm(Hh, Hl, OT_WQ + (long)l*DD*DD, Q,  BT, DD, DD, 0, nullptr, 1, 0,0,0,0, 2);
        hgemm(Hh, Hl, OT_WK + (long)l*DD*DD, Kb, BT, DD, DD, 0, nullptr, 1, 0,0,0,0, 2);
        hgemm(Hh, Hl, OT_WV + (long)l*DD*DD, Vb, BT, DD, DD, 0, nullptr, 1, 0,0,0,0, 2);
        rope_kernel<<<(BT*HT*32)/256, 256>>>(Q, Kb, TT, HT, DD, BT);
        attn_kernel<<<dim3(TT/64, BB*HT, 1), 256, ATTN_SMEM>>>(Q, Kb, Vb, Oh, Ol, TT, HT, DD, 0);
        hgemm(Oh, Ol, OT_WO + (long)l*DD*DD, X, BT, DD, DD, 1, nullptr, 1, 0,0,0,0, 2);
        rms_kernel<<<BT, 256>>>(X, t_n2 + (long)l*DD, Hh, Hl, DD, BT, 0);
        hgemm(Hh, Hl, OT_W1 + (long)l*DD*DFF, M1, BT, DFF, DD, 0, nullptr, 1, 0,0,0,0, 2);
        gelu_kernel<<<(BT*DFF/4)/256, 256>>>(M1, M1h, M1l, BT*DFF/4);
        hgemm(M1h, M1l, OT_W2 + (long)l*DFF*DD, X, BT, DD, DFF, 1, nullptr, 1, 0,0,0,0, 2);
    }

    // ---- column projection ----
    split2_kernel<<<(BT*DD/4)/256, 256>>>(X, Hh, Hl, BT*DD/4);
    hgemm(Hh, Hl, OC_IN, CS, BT, DC, DD, 0, cin_b, CC, 0, (long)DD*DC, (long)BT*DC, DC, 2);

    // ---- column layers ----
    for (int l = 0; l < LC; l++) {
        rms_kernel<<<CBT, 256>>>(CS, c_n1 + (long)l*DC, Hh, Hl, DC, BT, (long)LC*DC);
        hgemm(Hh, Hl, OC_WQ + (long)l*DC*DC, Q,  BT, DC, DC, 0, nullptr, CC,
              (long)BT*DC, (long)LC*DC*DC, (long)BT*DC, 0, 2);
        hgemm(Hh, Hl, OC_WK + (long)l*DC*DC, Kb, BT, DC, DC, 0, nullptr, CC,
              (long)BT*DC, (long)LC*DC*DC, (long)BT*DC, 0, 2);
        hgemm(Hh, Hl, OC_WV + (long)l*DC*DC, Vb, BT, DC, DC, 0, nullptr, CC,
              (long)BT*DC, (long)LC*DC*DC, (long)BT*DC, 0, 2);
        rope_kernel<<<(CBT*HC*32)/256, 256>>>(Q, Kb, TT, HC, DC, CBT);
        attn_kernel<<<dim3(TT/64, BB*HC, CC), 256, ATTN_SMEM>>>(Q, Kb, Vb, Oh, Ol, TT, HC, DC, (long)BT*DC);
        hgemm(Oh, Ol, OC_WO + (long)l*DC*DC, CS, BT, DC, DC, 1, nullptr, CC,
              (long)BT*DC, (long)LC*DC*DC, (long)BT*DC, 0, 2);
        rms_kernel<<<CBT, 256>>>(CS, c_n2 + (long)l*DC, Hh, Hl, DC, BT, (long)LC*DC);
        hgemm(Hh, Hl, OC_W1 + (long)l*DC*DFFC, M1, BT, DFFC, DC, 0, nullptr, CC,
              (long)BT*DC, (long)LC*DC*DFFC, (long)BT*DFFC, 0, 2);
        gelu_kernel<<<(CBT*DFFC/4)/256, 256>>>(M1, M1h, M1l, CBT*DFFC/4);
        hgemm(M1h, M1l, OC_W2 + (long)l*DFFC*DC, CS, BT, DC, DFFC, 1, nullptr, CC,
              (long)BT*DFFC, (long)LC*DFFC*DC, (long)BT*DC, 0, 2);

        if (((l + 1) & 1) == 0) {
            int m = (l + 1)/2 - 1;
            rms_kernel<<<CBT, 256>>>(CS, m_n + (long)m*DC, Hh, Hl, DC, CBT, 0);
            hgemm(Hh, Hl, OM_WQ + (long)m*DC*DC, Q,  CBT, DC, DC, 0, nullptr, 1, 0,0,0,0, 2);
            hgemm(Hh, Hl, OM_WK + (long)m*DC*DC, Kb, CBT, DC, DC, 0, nullptr, 1, 0,0,0,0, 2);
            hgemm(Hh, Hl, OM_WV + (long)m*DC*DC, Vb, CBT, DC, DC, 0, nullptr, 1, 0,0,0,0, 2);
            merge_attn_kernel<<<(CC*BT*HC)/256, 256>>>(Q, Kb, Vb, Oh, Ol);
            hgemm(Oh, Ol, OM_WO + (long)m*DC*DC, CS, CBT, DC, DC, 1, nullptr, 1, 0,0,0,0, 2);
        }
    }

    // ---- output head ----
    comb_kernel<<<(BT*DD/4)/256, 256>>>(CS, Hh, Hl);
    hgemm(Hh, Hl, O_OP, Q, BT, DD, DD, 0, nullptr, 1, 0,0,0,0, 2);
    rms_kernel<<<BT, 256>>>(Q, fnorm, Hh, Hl, DD, BT, 0);
    hgemm(Hh, nullptr, O_EMB, out, BT, BV, DD, 0, nullptr, 1, 0,0,0,0, 1);
}

// round 3
// speedup vs baseline: 2.8330x; 1.4516x over previous
#include <cuda_runtime.h>
#include <cuda_fp16.h>
#include <math.h>
#include <stdint.h>

// ---------------- model constants ----------------
#define BV   32000
#define DD   1024
#define DFF  4096
#define LT   2
#define HT   16
#define CC   4
#define DC   256
#define DFFC 1024
#define LC   4
#define HC   4
#define NM   2
#define BB   2
#define TT   1024
#define BT   (BB*TT)     // 2048
#define CBT  (CC*BT)     // 8192

// ---------------- weight offsets (transposed [N][K] fp16 store) ----------------
constexpr long OT_WQ = 0;
constexpr long OT_WK = OT_WQ + (long)LT*DD*DD;
constexpr long OT_WV = OT_WK + (long)LT*DD*DD;
constexpr long OT_WO = OT_WV + (long)LT*DD*DD;
constexpr long OT_W1 = OT_WO + (long)LT*DD*DD;
constexpr long OT_W2 = OT_W1 + (long)LT*DD*DFF;
constexpr long OC_IN = OT_W2 + (long)LT*DFF*DD;
constexpr long OC_WQ = OC_IN + (long)CC*DD*DC;
constexpr long OC_WK = OC_WQ + (long)CC*LC*DC*DC;
constexpr long OC_WV = OC_WK + (long)CC*LC*DC*DC;
constexpr long OC_WO = OC_WV + (long)CC*LC*DC*DC;
constexpr long OC_W1 = OC_WO + (long)CC*LC*DC*DC;
constexpr long OC_W2 = OC_W1 + (long)CC*LC*DC*DFFC;
constexpr long OM_WQ = OC_W2 + (long)CC*LC*DFFC*DC;
constexpr long OM_WK = OM_WQ + (long)NM*DC*DC;
constexpr long OM_WV = OM_WK + (long)NM*DC*DC;
constexpr long OM_WO = OM_WV + (long)NM*DC*DC;
constexpr long O_OP  = OM_WO + (long)NM*DC*DC;
constexpr long O_EMB = O_OP  + (long)DD*DD;
constexpr long WTOT  = O_EMB + (long)BV*DD;

// ---------------- scratch (device globals) ----------------
__device__ float  g_X [BT*DD];
__device__ float  g_Q [BT*DD];
__device__ float  g_K [BT*DD];
__device__ float  g_V [BT*DD];
__device__ float  g_M1[BT*DFF];
__device__ float  g_CS[CC*BT*DC];
__device__ __half g_Hh[BT*DD];
__device__ __half g_Hl[BT*DD];
__device__ __half g_M1h[BT*DFF];
__device__ __half g_M1l[BT*DFF];
__device__ __half g_Oh[BT*DD];
__device__ __half g_Ol[BT*DD];
__device__ __half g_Qh[BT*DD];
__device__ __half g_Ql[BT*DD];
__device__ __half g_Kh[BT*DD];
__device__ __half g_Kl[BT*DD];
__device__ __half g_Vh[BT*DD];
__device__ __half g_Vl[BT*DD];
__device__ __half g_Wh[WTOT];
__device__ __half g_Wl[WTOT];

// ---------------- asm helpers ----------------
__device__ __forceinline__ void lm4(const __half* p, uint32_t* r)
{
    uint32_t a = (uint32_t)__cvta_generic_to_shared(p);
    asm volatile("ldmatrix.sync.aligned.m8n8.x4.shared.b16 {%0,%1,%2,%3}, [%4];"
        : "=r"(r[0]), "=r"(r[1]), "=r"(r[2]), "=r"(r[3]) : "r"(a));
}
__device__ __forceinline__ void lm4t(const __half* p, uint32_t* r)
{
    uint32_t a = (uint32_t)__cvta_generic_to_shared(p);
    asm volatile("ldmatrix.sync.aligned.m8n8.x4.trans.shared.b16 {%0,%1,%2,%3}, [%4];"
        : "=r"(r[0]), "=r"(r[1]), "=r"(r[2]), "=r"(r[3]) : "r"(a));
}
__device__ __forceinline__ void mma16816(float* c, const uint32_t* a, const uint32_t* b)
{
    asm volatile("mma.sync.aligned.m16n8k16.row.col.f32.f16.f16.f32 "
        "{%0,%1,%2,%3},{%4,%5,%6,%7},{%8,%9},{%0,%1,%2,%3};"
        : "+f"(c[0]), "+f"(c[1]), "+f"(c[2]), "+f"(c[3])
        : "r"(a[0]), "r"(a[1]), "r"(a[2]), "r"(a[3]), "r"(b[0]), "r"(b[1]));
}
__device__ __forceinline__ void cpasync16(const __half* dst, const __half* src)
{
    uint32_t d = (uint32_t)__cvta_generic_to_shared(dst);
    asm volatile("cp.async.cg.shared.global [%0], [%1], 16;" :: "r"(d), "l"(src));
}
__device__ __forceinline__ void cp_commit() { asm volatile("cp.async.commit_group;"); }
template<int N> __device__ __forceinline__ void cp_wait()
{ asm volatile("cp.async.wait_group %0;" :: "n"(N)); }

// ---------------- HGEMM (cp.async double-buffered) ----------------
// A: [M][K] rm, B: [N][K] rm, C: [M][N] fp32.  NT=2: hi/lo split, NT=1: plain.
#define BM 128
#define BN 128
#define BKH 32
#define SSTR 40
#define GPER (BM*SSTR)

template<int NT>
__global__ void __launch_bounds__(256) hgemm_kernel(
    const __half* __restrict__ Ah, const __half* __restrict__ Al,
    const __half* __restrict__ Bh, const __half* __restrict__ Bl,
    const float* __restrict__ bias, float* __restrict__ C,
    int M, int N, int K, int accum,
    long aBS, long bBS, long cBS, long biasBS)
{
    extern __shared__ __half smp[];
    const int NARR = (NT == 2) ? 4 : 2;

    Ah += blockIdx.z * aBS;
    Bh += blockIdx.z * bBS;
    C  += blockIdx.z * cBS;
    if (NT == 2) { Al += blockIdx.z * aBS; Bl += blockIdx.z * bBS; }
    if (bias) bias += blockIdx.z * biasBS;

    int row0 = blockIdx.y * BM;
    int col0 = blockIdx.x * BN;
    int tid  = threadIdx.x;
    int lane = tid & 31;
    int wid  = tid >> 5;
    int wm0  = (wid >> 2) * 64;
    int wn0  = (wid & 3) * 32;

    float acc[4][4][4];
#pragma unroll
    for (int mt = 0; mt < 4; mt++)
#pragma unroll
        for (int nt = 0; nt < 4; nt++)
#pragma unroll
            for (int q = 0; q < 4; q++) acc[mt][nt][q] = 0.f;

    int a_r  = lane & 15;
    int a_ko = (lane >> 4) << 3;
    int b_n  = ((lane >> 4) << 3) + (lane & 7);
    int b_ko = ((lane >> 3) & 1) << 3;

    int nk = K / BKH;

    // stage load
    auto loadStage = [&](int st, int k0) {
        __half* dAh = smp + st * NARR * GPER;
        __half* dBh = dAh + GPER;
        __half* dAl = dAh + 2 * GPER;
        __half* dBl = dAh + 3 * GPER;
#pragma unroll
        for (int c = tid; c < 512; c += 256) {
            int r = c >> 2, o = (c & 3) << 3;
            cpasync16(&dAh[r*SSTR + o], &Ah[(long)(row0 + r)*K + k0 + o]);
            cpasync16(&dBh[r*SSTR + o], &Bh[(long)(col0 + r)*K + k0 + o]);
            if (NT == 2) {
                cpasync16(&dAl[r*SSTR + o], &Al[(long)(row0 + r)*K + k0 + o]);
                cpasync16(&dBl[r*SSTR + o], &Bl[(long)(col0 + r)*K + k0 + o]);
            }
        }
    };

    loadStage(0, 0);
    cp_commit();

    for (int kt = 0; kt < nk; kt++) {
        int cur = kt & 1;
        if (kt + 1 < nk) {
            loadStage(cur ^ 1, (kt + 1) * BKH);
            cp_commit();
            cp_wait<1>();
        } else {
            cp_wait<0>();
        }
        __syncthreads();

        const __half* pAh = smp + cur * NARR * GPER;
        const __half* pBh = pAh + GPER;
        const __half* pAl = pAh + 2 * GPER;
        const __half* pBl = pAh + 3 * GPER;

#pragma unroll
        for (int ks = 0; ks < BKH; ks += 16) {
            uint32_t a_hi[4][4], b_hi[2][4];
#pragma unroll
            for (int mt = 0; mt < 4; mt++)
                lm4(&pAh[(wm0 + mt*16 + a_r)*SSTR + ks + a_ko], a_hi[mt]);
#pragma unroll
            for (int np = 0; np < 2; np++)
                lm4(&pBh[(wn0 + np*16 + b_n)*SSTR + ks + b_ko], b_hi[np]);
#pragma unroll
            for (int mt = 0; mt < 4; mt++)
#pragma unroll
                for (int nt = 0; nt < 4; nt++)
                    mma16816(acc[mt][nt], a_hi[mt], &b_hi[nt >> 1][(nt & 1)*2]);

            if (NT == 2) {
                uint32_t b_lo[2][4];
#pragma unroll
                for (int np = 0; np < 2; np++)
                    lm4(&pBl[(wn0 + np*16 + b_n)*SSTR + ks + b_ko], b_lo[np]);
#pragma unroll
                for (int mt = 0; mt < 4; mt++)
#pragma unroll
                    for (int nt = 0; nt < 4; nt++)
                        mma16816(acc[mt][nt], a_hi[mt], &b_lo[nt >> 1][(nt & 1)*2]);
                uint32_t a_lo[4][4];
#pragma unroll
                for (int mt = 0; mt < 4; mt++)
                    lm4(&pAl[(wm0 + mt*16 + a_r)*SSTR + ks + a_ko], a_lo[mt]);
#pragma unroll
                for (int mt = 0; mt < 4; mt++)
#pragma unroll
                    for (int nt = 0; nt < 4; nt++)
                        mma16816(acc[mt][nt], a_lo[mt], &b_hi[nt >> 1][(nt & 1)*2]);
            }
        }
        __syncthreads();
    }

    int g = lane >> 2, t = lane & 3;
#pragma unroll
    for (int mt = 0; mt < 4; mt++) {
#pragma unroll
        for (int nt = 0; nt < 4; nt++) {
            int r1  = row0 + wm0 + mt*16 + g;
            int cix = col0 + wn0 + nt*8 + 2*t;
            float bv0 = 0.f, bv1 = 0.f;
            if (bias) { bv0 = bias[cix]; bv1 = bias[cix + 1]; }
            float2 v0 = make_float2(acc[mt][nt][0] + bv0, acc[mt][nt][1] + bv1);
            float2 v1 = make_float2(acc[mt][nt][2] + bv0, acc[mt][nt][3] + bv1);
            long o0 = (long)r1*N + cix;
            long o1 = (long)(r1 + 8)*N + cix;
            if (accum) {
                float2 p0 = *(float2*)&C[o0];
                float2 p1 = *(float2*)&C[o1];
                v0.x += p0.x; v0.y += p0.y;
                v1.x += p1.x; v1.y += p1.y;
            }
            *(float2*)&C[o0] = v0;
            *(float2*)&C[o1] = v1;
        }
    }
}

// ---------------- tensor-core flash attention (causal, hd=64) ----------------
#define ASTR 72
#define FATTN_SMEM (6*64*ASTR*2)

__global__ void __launch_bounds__(128) fattn_kernel(
    const __half* __restrict__ Qh, const __half* __restrict__ Ql,
    const __half* __restrict__ Kh, const __half* __restrict__ Kl,
    const __half* __restrict__ Vh, const __half* __restrict__ Vl,
    __half* __restrict__ Oh, __half* __restrict__ Ol,
    int T, int nh, int rstride, long colstride)
{
    extern __shared__ __half sm[];
    __half* sQh = sm;
    __half* sQl = sQh + 64*ASTR;
    __half* sKh = sQl + 64*ASTR;
    __half* sKl = sKh + 64*ASTR;
    __half* sVh = sKl + 64*ASTR;
    __half* sVl = sVh + 64*ASTR;

    int qt = blockIdx.x;
    int b  = blockIdx.y / nh;
    int h  = blockIdx.y % nh;
    long base = (long)blockIdx.z * colstride + (long)h * 64;
    int q0  = qt * 64;
    int tid = threadIdx.x;
    int lane = tid & 31;
    int wid  = tid >> 5;
    int wrow = wid * 16;
    int g = lane >> 2, t4 = lane & 3;

    // load Q tile hi/lo
#pragma unroll
    for (int c = tid; c < 512; c += 128) {
        int r = c >> 3, o = (c & 7) << 3;
        long src = base + (long)(b*T + q0 + r)*rstride + o;
        *(uint4*)&sQh[r*ASTR + o] = *(const uint4*)&Qh[src];
        *(uint4*)&sQl[r*ASTR + o] = *(const uint4*)&Ql[src];
    }
    __syncthreads();

    int a_r  = lane & 15;
    int a_ko = (lane >> 4) << 3;
    int b_n  = ((lane >> 4) << 3) + (lane & 7);
    int b_ko = ((lane >> 3) & 1) << 3;
    int v_r  = (((lane >> 3) & 1) << 3) + (lane & 7);
    int v_c  = (lane >> 4) << 3;

    uint32_t qfh[4][4], qfl[4][4];
#pragma unroll
    for (int ks = 0; ks < 4; ks++) {
        lm4(&sQh[(wrow + a_r)*ASTR + ks*16 + a_ko], qfh[ks]);
        lm4(&sQl[(wrow + a_r)*ASTR + ks*16 + a_ko], qfl[ks]);
    }

    float mrow[2] = {-1e30f, -1e30f};
    float lrow[2] = {0.f, 0.f};
    float oacc[8][4];
#pragma unroll
    for (int nt = 0; nt < 8; nt++)
#pragma unroll
        for (int e = 0; e < 4; e++) oacc[nt][e] = 0.f;

    for (int kt = 0; kt <= qt; kt++) {
        int k0 = kt * 64;
        __syncthreads();
#pragma unroll
        for (int c = tid; c < 512; c += 128) {
            int r = c >> 3, o = (c & 7) << 3;
            long src = base + (long)(b*T + k0 + r)*rstride + o;
            *(uint4*)&sKh[r*ASTR + o] = *(const uint4*)&Kh[src];
            *(uint4*)&sKl[r*ASTR + o] = *(const uint4*)&Kl[src];
            *(uint4*)&sVh[r*ASTR + o] = *(const uint4*)&Vh[src];
            *(uint4*)&sVl[r*ASTR + o] = *(const uint4*)&Vl[src];
        }
        __syncthreads();

        float S[8][4];
#pragma unroll
        for (int nt = 0; nt < 8; nt++)
#pragma unroll
            for (int e = 0; e < 4; e++) S[nt][e] = 0.f;

#pragma unroll
        for (int ks = 0; ks < 4; ks++) {
            uint32_t bh[4][4], bl[4][4];
#pragma unroll
            for (int np = 0; np < 4; np++) {
                lm4(&sKh[(np*16 + b_n)*ASTR + ks*16 + b_ko], bh[np]);
                lm4(&sKl[(np*16 + b_n)*ASTR + ks*16 + b_ko], bl[np]);
            }
#pragma unroll
            for (int np = 0; np < 4; np++)
#pragma unroll
                for (int j = 0; j < 2; j++) {
                    int nt = np*2 + j;
                    mma16816(S[nt], qfh[ks], &bh[np][j*2]);
                    mma16816(S[nt], qfh[ks], &bl[np][j*2]);
                    mma16816(S[nt], qfl[ks], &bh[np][j*2]);
                }
        }

        // scale + causal mask
#pragma unroll
        for (int nt = 0; nt < 8; nt++)
#pragma unroll
            for (int e = 0; e < 4; e++) {
                S[nt][e] *= 0.125f;
                if (kt == qt) {
                    int col = k0 + nt*8 + t4*2 + (e & 1);
                    int row = q0 + wrow + g + ((e >> 1) << 3);
                    if (col > row) S[nt][e] = -1e30f;
                }
            }

        // online softmax (rows g, g+8)
        float P[8][4];
#pragma unroll
        for (int r = 0; r < 2; r++) {
            float mx = -1e30f;
#pragma unroll
            for (int nt = 0; nt < 8; nt++) {
                mx = fmaxf(mx, S[nt][2*r + 0]);
                mx = fmaxf(mx, S[nt][2*r + 1]);
            }
            mx = fmaxf(mx, __shfl_xor_sync(0xffffffffu, mx, 1));
            mx = fmaxf(mx, __shfl_xor_sync(0xffffffffu, mx, 2));
            float mnew  = fmaxf(mrow[r], mx);
            float alpha = __expf(mrow[r] - mnew);
            float rsum = 0.f;
#pragma unroll
            for (int nt = 0; nt < 8; nt++) {
                float p0 = __expf(S[nt][2*r + 0] - mnew);
                float p1 = __expf(S[nt][2*r + 1] - mnew);
                P[nt][2*r + 0] = p0; P[nt][2*r + 1] = p1;
                rsum += p0 + p1;
            }
            rsum += __shfl_xor_sync(0xffffffffu, rsum, 1);
            rsum += __shfl_xor_sync(0xffffffffu, rsum, 2);
            lrow[r] = lrow[r]*alpha + rsum;
            mrow[r] = mnew;
#pragma unroll
            for (int nt = 0; nt < 8; nt++) {
                oacc[nt][2*r + 0] *= alpha;
                oacc[nt][2*r + 1] *= alpha;
            }
        }

        // pack P into A-fragments (hi + lo)
        uint32_t pah[4][4], pal[4][4];
#pragma unroll
        for (int ks = 0; ks < 4; ks++) {
            int j0 = 2*ks, j1 = 2*ks + 1;
#pragma unroll
            for (int q = 0; q < 4; q++) {
                int jj = (q < 2) ? j0 : j1;
                int e0 = (q & 1) ? 2 : 0;
                float f0 = P[jj][e0], f1 = P[jj][e0 + 1];
                __half h0 = __float2half(f0), h1 = __float2half(f1);
                __half l0 = __float2half(f0 - __half2float(h0));
                __half l1 = __float2half(f1 - __half2float(h1));
                pah[ks][q] = (uint32_t)__half_as_ushort(h0) |
                             ((uint32_t)__half_as_ushort(h1) << 16);
                pal[ks][q] = (uint32_t)__half_as_ushort(l0) |
                             ((uint32_t)__half_as_ushort(l1) << 16);
            }
        }

        // O += P @ V
#pragma unroll
        for (int ks = 0; ks < 4; ks++) {
            uint32_t vh[4][4], vl[4][4];
#pragma unroll
            for (int np = 0; np < 4; np++) {
                lm4t(&sVh[(ks*16 + v_r)*ASTR + np*16 + v_c], vh[np]);
                lm4t(&sVl[(ks*16 + v_r)*ASTR + np*16 + v_c], vl[np]);
            }
#pragma unroll
            for (int np = 0; np < 4; np++)
#pragma unroll
                for (int j = 0; j < 2; j++) {
                    int nt = np*2 + j;
                    mma16816(oacc[nt], pah[ks], &vh[np][j*2]);
                    mma16816(oacc[nt], pah[ks], &vl[np][j*2]);
                    mma16816(oacc[nt], pal[ks], &vh[np][j*2]);
                }
        }
    }

    // write output (hi/lo split)
#pragma unroll
    for (int r = 0; r < 2; r++) {
        float inv = 1.f / lrow[r];
        int row = q0 + wrow + g + r*8;
        long ob = base + (long)(b*T + row)*rstride;
#pragma unroll
        for (int nt = 0; nt < 8; nt++) {
            float v0 = oacc[nt][2*r + 0] * inv;
            float v1 = oacc[nt][2*r + 1] * inv;
            __half h0 = __float2half(v0), h1 = __float2half(v1);
            __half l0 = __float2half(v0 - __half2float(h0));
            __half l1 = __float2half(v1 - __half2float(h1));
            int col = nt*8 + t4*2;
            *(__half2*)&Oh[ob + col] = __halves2half2(h0, h1);
            *(__half2*)&Ol[ob + col] = __halves2half2(l0, l1);
        }
    }
}

// ---------------- weight transpose + fp16 split ----------------
__global__ void splitT_kernel(const float* __restrict__ in, __half* __restrict__ oh,
                              __half* __restrict__ ol, int K, int N,
                              long inStride, long outStride)
{
    __shared__ float tile[32][33];
    in += blockIdx.z * inStride;
    long ob = blockIdx.z * outStride;
    int n0 = blockIdx.x * 32, k0 = blockIdx.y * 32;
    int tx = threadIdx.x & 31, ty = threadIdx.x >> 5;
#pragma unroll
    for (int j = 0; j < 4; j++) {
        int r = ty*4 + j;
        tile[r][tx] = in[(long)(k0 + r)*N + n0 + tx];
    }
    __syncthreads();
#pragma unroll
    for (int j = 0; j < 4; j++) {
        int nn = ty*4 + j;
        float v = tile[tx][nn];
        __half h = __float2half(v);
        long o = ob + (long)(n0 + nn)*K + k0 + tx;
        oh[o] = h;
        ol[o] = __float2half(v - __half2float(h));
    }
}

__global__ void split1_kernel(const float* __restrict__ in, __half* __restrict__ oh, int n4)
{
    int i = blockIdx.x * blockDim.x + threadIdx.x;
    if (i >= n4) return;
    float4 v = ((const float4*)in)[i];
    oh[4*i + 0] = __float2half(v.x);
    oh[4*i + 1] = __float2half(v.y);
    oh[4*i + 2] = __float2half(v.z);
    oh[4*i + 3] = __float2half(v.w);
}

__device__ __forceinline__ void split_store(__half* oh, __half* ol, long idx, float v)
{
    __half h = __float2half(v);
    oh[idx] = h;
    ol[idx] = __float2half(v - __half2float(h));
}
__global__ void split2_kernel(const float* __restrict__ in, __half* __restrict__ oh,
                              __half* __restrict__ ol, int n4)
{
    int i = blockIdx.x * blockDim.x + threadIdx.x;
    if (i >= n4) return;
    float4 v = ((const float4*)in)[i];
    split_store(oh, ol, 4L*i + 0, v.x);
    split_store(oh, ol, 4L*i + 1, v.y);
    split_store(oh, ol, 4L*i + 2, v.z);
    split_store(oh, ol, 4L*i + 3, v.w);
}

// ---------------- rmsnorm -> fp16 hi/lo ----------------
__global__ void rms_kernel(const float* __restrict__ x, const float* __restrict__ w,
                           __half* __restrict__ oh, __half* __restrict__ ol,
                           int W, int rowsPerChunk, long wStride)
{
    int row = blockIdx.x;
    const float* xr = x + (long)row * W;
    const float* wr = w + (long)(row / rowsPerChunk) * wStride;
    float ss = 0.f;
    for (int i = threadIdx.x; i < W; i += 256) {
        float v = xr[i];
        ss += v * v;
    }
    __shared__ float red[8];
#pragma unroll
    for (int off = 16; off > 0; off >>= 1)
        ss += __shfl_xor_sync(0xffffffffu, ss, off);
    if ((threadIdx.x & 31) == 0) red[threadIdx.x >> 5] = ss;
    __syncthreads();
    float tot = red[0]+red[1]+red[2]+red[3]+red[4]+red[5]+red[6]+red[7];
    float inv = rsqrtf(tot / (float)W + 1e-6f);
    long rb = (long)row * W;
    for (int i = threadIdx.x; i < W; i += 256)
        split_store(oh, ol, rb + i, xr[i] * inv * wr[i]);
}

// ---------------- rope: fp32 q,k -> rotated fp16 hi/lo ----------------
__global__ void rope_kernel(const float* __restrict__ q, const float* __restrict__ k,
                            __half* __restrict__ qh, __half* __restrict__ ql,
                            __half* __restrict__ kh, __half* __restrict__ kl,
                            int T, int nh, int rstride, int nrows)
{
    int idx = blockIdx.x * blockDim.x + threadIdx.x;
    if (idx >= nrows * nh * 32) return;
    int i   = idx & 31;
    int h   = (idx >> 5) % nh;
    int row = idx / (32 * nh);
    int t   = row % T;
    float inv = __expf(-(float)(2*i) * (1.f/64.f) * 9.210340371976184f);
    float f = (float)t * inv;
    float s, c;
    sincosf(f, &s, &c);
    long bo = (long)row * rstride + h*64 + i;
    float q1 = q[bo], q2 = q[bo + 32];
    split_store(qh, ql, bo,      q1*c - q2*s);
    split_store(qh, ql, bo + 32, q2*c + q1*s);
    float k1 = k[bo], k2 = k[bo + 32];
    split_store(kh, kl, bo,      k1*c - k2*s);
    split_store(kh, kl, bo + 32, k2*c + k1*s);
}

// ---------------- gelu ----------------
__device__ __forceinline__ float gelu1(float v)
{
    return 0.5f * v * (1.f + tanhf(0.7978845608028654f * (v + 0.044715f*v*v*v)));
}
__global__ void gelu_kernel(const float* __restrict__ x, __half* __restrict__ oh,
                            __half* __restrict__ ol, int n4)
{
    int i = blockIdx.x * blockDim.x + threadIdx.x;
    if (i >= n4) return;
    float4 v = ((const float4*)x)[i];
    split_store(oh, ol, 4L*i + 0, gelu1(v.x));
    split_store(oh, ol, 4L*i + 1, gelu1(v.y));
    split_store(oh, ol, 4L*i + 2, gelu1(v.z));
    split_store(oh, ol, 4L*i + 3, gelu1(v.w));
}

// ---------------- embedding gather ----------------
__global__ void embed_kernel(float* __restrict__ X, const float* __restrict__ emb,
                             const int* __restrict__ ids)
{
    int row = blockIdx.x;
    int id  = ids[row];
    const float4* src = (const float4*)(emb + (long)id * DD);
    float4* dst = (float4*)(X + (long)row * DD);
    dst[threadIdx.x] = src[threadIdx.x];
}

// ---------------- cross-column merge attention ----------------
__global__ void merge_attn_kernel(const float* __restrict__ Qm, const float* __restrict__ Km,
                                  const float* __restrict__ Vm,
                                  __half* __restrict__ Oh, __half* __restrict__ Ol)
{
    int gid = blockIdx.x * blockDim.x + threadIdx.x;
    int h   = gid & 3;
    int row = (gid >> 2) & (BT - 1);
    int i   = gid >> 13;
    if (i >= CC) return;
    long base  = (long)row * DC + h*64;
    long cstep = (long)BT * DC;

    float4 q[16];
    const float4* qp = (const float4*)(Qm + i*cstep + base);
#pragma unroll
    for (int t = 0; t < 16; t++) q[t] = qp[t];

    float s[CC];
#pragma unroll
    for (int j = 0; j < CC; j++) {
        const float4* kp = (const float4*)(Km + j*cstep + base);
        float acc = 0.f;
#pragma unroll
        for (int t = 0; t < 16; t++) {
            float4 kv = kp[t];
            acc += q[t].x*kv.x + q[t].y*kv.y + q[t].z*kv.z + q[t].w*kv.w;
        }
        s[j] = acc * 0.125f;
    }
    float mm = fmaxf(fmaxf(s[0], s[1]), fmaxf(s[2], s[3]));
    float a[CC], sum = 0.f;
#pragma unroll
    for (int j = 0; j < CC; j++) { a[j] = __expf(s[j] - mm); sum += a[j]; }
    float isum = 1.f / sum;
#pragma unroll
    for (int j = 0; j < CC; j++) a[j] *= isum;

    float o[64];
#pragma unroll
    for (int t = 0; t < 64; t++) o[t] = 0.f;
#pragma unroll
    for (int j = 0; j < CC; j++) {
        const float4* vp = (const float4*)(Vm + j*cstep + base);
        float aj = a[j];
#pragma unroll
        for (int t = 0; t < 16; t++) {
            float4 vv = vp[t];
            o[4*t+0] = fmaf(aj, vv.x, o[4*t+0]);
            o[4*t+1] = fmaf(aj, vv.y, o[4*t+1]);
            o[4*t+2] = fmaf(aj, vv.z, o[4*t+2]);
            o[4*t+3] = fmaf(aj, vv.w, o[4*t+3]);
        }
    }
    long ob = i*cstep + base;
#pragma unroll
    for (int t = 0; t < 64; t++) split_store(Oh, Ol, ob + t, o[t]);
}

// ---------------- concat ----------------
__global__ void comb_kernel(const float* __restrict__ cs, __half* __restrict__ oh,
                            __half* __restrict__ ol)
{
    int gid = blockIdx.x * blockDim.x + threadIdx.x;
    int d4  = gid & (DD/4 - 1);
    int row = gid / (DD/4);
    int d = d4 * 4;
    int c = d >> 8;
    int e = d & 255;
    float4 v = *(const float4*)(cs + (long)c*BT*DC + (long)row*DC + e);
    split_store(oh, ol, 4L*gid + 0, v.x);
    split_store(oh, ol, 4L*gid + 1, v.y);
    split_store(oh, ol, 4L*gid + 2, v.z);
    split_store(oh, ol, 4L*gid + 3, v.w);
}

// ---------------- host side ----------------
static __half *Wh_p, *Wl_p;
#define HG2_SMEM (2*4*GPER*2)
#define HG1_SMEM (2*2*GPER*2)

static inline void hgemm(const __half* Ah, const __half* Al, long boff, float* C,
                         int M, int N, int K, int accum, const float* bias, int batch,
                         long aBS, long bBS, long cBS, long biasBS, int nt)
{
    dim3 grid(N/BN, M/BM, batch);
    if (nt == 2)
        hgemm_kernel<2><<<grid, 256, HG2_SMEM>>>(Ah, Al, Wh_p + boff, Wl_p + boff, bias, C,
                                                 M, N, K, accum, aBS, bBS, cBS, biasBS);
    else
        hgemm_kernel<1><<<grid, 256, HG1_SMEM>>>(Ah, nullptr, Wh_p + boff, nullptr, bias, C,
                                                 M, N, K, accum, aBS, bBS, cBS, biasBS);
}

static inline void splitT(const float* in, long off, int K, int N, int batch)
{
    splitT_kernel<<<dim3(N/32, K/32, batch), 256>>>(in, Wh_p + off, Wl_p + off,
                                                    K, N, (long)K*N, (long)K*N);
}

extern "C" void kernel_launch(void* const* d_in, const int* in_sizes, int n_in,
                              void* d_out, int out_size)
{
    const int*   ids   = (const int*)d_in[0];
    const float* emb   = (const float*)d_in[1];
    const float* t_wq  = (const float*)d_in[2];
    const float* t_wk  = (const float*)d_in[3];
    const float* t_wv  = (const float*)d_in[4];
    const float* t_wo  = (const float*)d_in[5];
    const float* t_w1  = (const float*)d_in[6];
    const float* t_w2  = (const float*)d_in[7];
    const float* t_n1  = (const float*)d_in[8];
    const float* t_n2  = (const float*)d_in[9];
    const float* cin_w = (const float*)d_in[10];
    const float* cin_b = (const float*)d_in[11];
    const float* c_wq  = (const float*)d_in[12];
    const float* c_wk  = (const float*)d_in[13];
    const float* c_wv  = (const float*)d_in[14];
    const float* c_wo  = (const float*)d_in[15];
    const float* c_w1  = (const float*)d_in[16];
    const float* c_w2  = (const float*)d_in[17];
    const float* c_n1  = (const float*)d_in[18];
    const float* c_n2  = (const float*)d_in[19];
    const float* m_wq  = (const float*)d_in[20];
    const float* m_wk  = (const float*)d_in[21];
    const float* m_wv  = (const float*)d_in[22];
    const float* m_wo  = (const float*)d_in[23];
    const float* m_n   = (const float*)d_in[24];
    const float* oproj = (const float*)d_in[25];
    const float* fnorm = (const float*)d_in[26];
    float* out = (float*)d_out;

    void* p;
    cudaGetSymbolAddress(&p, g_X);   float*  X   = (float*)p;
    cudaGetSymbolAddress(&p, g_Q);   float*  Q   = (float*)p;
    cudaGetSymbolAddress(&p, g_K);   float*  Kb  = (float*)p;
    cudaGetSymbolAddress(&p, g_V);   float*  Vb  = (float*)p;
    cudaGetSymbolAddress(&p, g_M1);  float*  M1  = (float*)p;
    cudaGetSymbolAddress(&p, g_CS);  float*  CS  = (float*)p;
    cudaGetSymbolAddress(&p, g_Hh);  __half* Hh  = (__half*)p;
    cudaGetSymbolAddress(&p, g_Hl);  __half* Hl  = (__half*)p;
    cudaGetSymbolAddress(&p, g_M1h); __half* M1h = (__half*)p;
    cudaGetSymbolAddress(&p, g_M1l); __half* M1l = (__half*)p;
    cudaGetSymbolAddress(&p, g_Oh);  __half* Oh  = (__half*)p;
    cudaGetSymbolAddress(&p, g_Ol);  __half* Ol  = (__half*)p;
    cudaGetSymbolAddress(&p, g_Qh);  __half* Qh  = (__half*)p;
    cudaGetSymbolAddress(&p, g_Ql);  __half* Ql  = (__half*)p;
    cudaGetSymbolAddress(&p, g_Kh);  __half* Kh  = (__half*)p;
    cudaGetSymbolAddress(&p, g_Kl);  __half* Kl  = (__half*)p;
    cudaGetSymbolAddress(&p, g_Vh);  __half* Vh  = (__half*)p;
    cudaGetSymbolAddress(&p, g_Vl);  __half* Vl  = (__half*)p;
    cudaGetSymbolAddress(&p, g_Wh);  Wh_p = (__half*)p;
    cudaGetSymbolAddress(&p, g_Wl);  Wl_p = (__half*)p;

    cudaFuncSetAttribute(hgemm_kernel<2>, cudaFuncAttributeMaxDynamicSharedMemorySize, HG2_SMEM);
    cudaFuncSetAttribute(hgemm_kernel<1>, cudaFuncAttributeMaxDynamicSharedMemorySize, HG1_SMEM);
    cudaFuncSetAttribute(fattn_kernel, cudaFuncAttributeMaxDynamicSharedMemorySize, FATTN_SMEM);

    // ---- weight conversion ----
    splitT(t_wq, OT_WQ, DD, DD, LT);
    splitT(t_wk, OT_WK, DD, DD, LT);
    splitT(t_wv, OT_WV, DD, DD, LT);
    splitT(t_wo, OT_WO, DD, DD, LT);
    splitT(t_w1, OT_W1, DD, DFF, LT);
    splitT(t_w2, OT_W2, DFF, DD, LT);
    splitT(cin_w, OC_IN, DD, DC, CC);
    splitT(c_wq, OC_WQ, DC, DC, CC*LC);
    splitT(c_wk, OC_WK, DC, DC, CC*LC);
    splitT(c_wv, OC_WV, DC, DC, CC*LC);
    splitT(c_wo, OC_WO, DC, DC, CC*LC);
    splitT(c_w1, OC_W1, DC, DFFC, CC*LC);
    splitT(c_w2, OC_W2, DFFC, DC, CC*LC);
    splitT(m_wq, OM_WQ, DC, DC, NM);
    splitT(m_wk, OM_WK, DC, DC, NM);
    splitT(m_wv, OM_WV, DC, DC, NM);
    splitT(m_wo, OM_WO, DC, DC, NM);
    splitT(oproj, O_OP, DD, DD, 1);
    split1_kernel<<<(BV*DD/4 + 255)/256, 256>>>(emb, Wh_p + O_EMB, BV*DD/4);

    embed_kernel<<<BT, 256>>>(X, emb, ids);

    // ---- trunk ----
    for (int l = 0; l < LT; l++) {
        rms_kernel<<<BT, 256>>>(X, t_n1 + (long)l*DD, Hh, Hl, DD, BT, 0);
        hgemm(Hh, Hl, OT_WQ + (long)l*DD*DD, Q,  BT, DD, DD, 0, nullptr, 1, 0,0,0,0, 2);
        hgemm(Hh, Hl, OT_WK + (long)l*DD*DD, Kb, BT, DD, DD, 0, nullptr, 1, 0,0,0,0, 2);
        hgemm(Hh, Hl, OT_WV + (long)l*DD*DD, Vb, BT, DD, DD, 0, nullptr, 1, 0,0,0,0, 2);
        rope_kernel<<<(BT*HT*32)/256, 256>>>(Q, Kb, Qh, Ql, Kh, Kl, TT, HT, DD, BT);
        split2_kernel<<<(BT*DD/4)/256, 256>>>(Vb, Vh, Vl, BT*DD/4);
        fattn_kernel<<<dim3(TT/64, BB*HT, 1), 128, FATTN_SMEM>>>(
            Qh, Ql, Kh, Kl, Vh, Vl, Oh, Ol, TT, HT, DD, 0);
        hgemm(Oh, Ol, OT_WO + (long)l*DD*DD, X, BT, DD, DD, 1, nullptr, 1, 0,0,0,0, 2);
        rms_kernel<<<BT, 256>>>(X, t_n2 + (long)l*DD, Hh, Hl, DD, BT, 0);
        hgemm(Hh, Hl, OT_W1 + (long)l*DD*DFF, M1, BT, DFF, DD, 0, nullptr, 1, 0,0,0,0, 2);
        gelu_kernel<<<(BT*DFF/4)/256, 256>>>(M1, M1h, M1l, BT*DFF/4);
        hgemm(M1h, M1l, OT_W2 + (long)l*DFF*DD, X, BT, DD, DFF, 1, nullptr, 1, 0,0,0,0, 2);
    }

    // ---- column projection ----
    split2_kernel<<<(BT*DD/4)/256, 256>>>(X, Hh, Hl, BT*DD/4);
    hgemm(Hh, Hl, OC_IN, CS, BT, DC, DD, 0, cin_b, CC, 0, (long)DD*DC, (long)BT*DC, DC, 2);

    // ---- column layers ----
    for (int l = 0; l < LC; l++) {
        rms_kernel<<<CBT, 256>>>(CS, c_n1 + (long)l*DC, Hh, Hl, DC, BT, (long)LC*DC);
        hgemm(Hh, Hl, OC_WQ + (long)l*DC*DC, Q,  BT, DC, DC, 0, nullptr, CC,
              (long)BT*DC, (long)LC*DC*DC, (long)BT*DC, 0, 2);
        hgemm(Hh, Hl, OC_WK + (long)l*DC*DC, Kb, BT, DC, DC, 0, nullptr, CC,
              (long)BT*DC, (long)LC*DC*DC, (long)BT*DC, 0, 2);
        hgemm(Hh, Hl, OC_WV + (long)l*DC*DC, Vb, BT, DC, DC, 0, nullptr, CC,
              (long)BT*DC, (long)LC*DC*DC, (long)BT*DC, 0, 2);
        rope_kernel<<<(CBT*HC*32)/256, 256>>>(Q, Kb, Qh, Ql, Kh, Kl, TT, HC, DC, CBT);
        split2_kernel<<<(CBT*DC/4)/256, 256>>>(Vb, Vh, Vl, CBT*DC/4);
        fattn_kernel<<<dim3(TT/64, BB*HC, CC), 128, FATTN_SMEM>>>(
            Qh, Ql, Kh, Kl, Vh, Vl, Oh, Ol, TT, HC, DC, (long)BT*DC);
        hgemm(Oh, Ol, OC_WO + (long)l*DC*DC, CS, BT, DC, DC, 1, nullptr, CC,
              (long)BT*DC, (long)LC*DC*DC, (long)BT*DC, 0, 2);
        rms_kernel<<<CBT, 256>>>(CS, c_n2 + (long)l*DC, Hh, Hl, DC, BT, (long)LC*DC);
        hgemm(Hh, Hl, OC_W1 + (long)l*DC*DFFC, M1, BT, DFFC, DC, 0, nullptr, CC,
              (long)BT*DC, (long)LC*DC*DFFC, (long)BT*DFFC, 0, 2);
        gelu_kernel<<<(CBT*DFFC/4)/256, 256>>>(M1, M1h, M1l, CBT*DFFC/4);
        hgemm(M1h, M1l, OC_W2 + (long)l*DFFC*DC, CS, BT, DC, DFFC, 1, nullptr, CC,
              (long)BT*DFFC, (long)LC*DFFC*DC, (long)BT*DC, 0, 2);

        if (((l + 1) & 1) == 0) {
            int m = (l + 1)/2 - 1;
            rms_kernel<<<CBT, 256>>>(CS, m_n + (long)m*DC, Hh, Hl, DC, CBT, 0);
            hgemm(Hh, Hl, OM_WQ + (long)m*DC*DC, Q,  CBT, DC, DC, 0, nullptr, 1, 0,0,0,0, 2);
            hgemm(Hh, Hl, OM_WK + (long)m*DC*DC, Kb, CBT, DC, DC, 0, nullptr, 1, 0,0,0,0, 2);
            hgemm(Hh, Hl, OM_WV + (long)m*DC*DC, Vb, CBT, DC, DC, 0, nullptr, 1, 0,0,0,0, 2);
            merge_attn_kernel<<<(CC*BT*HC)/256, 256>>>(Q, Kb, Vb, Oh, Ol);
            hgemm(Oh, Ol, OM_WO + (long)m*DC*DC, CS, CBT, DC, DC, 1, nullptr, 1, 0,0,0,0, 2);
        }
    }

    // ---- output head ----
    comb_kernel<<<(BT*DD/4)/256, 256>>>(CS, Hh, Hl);
    hgemm(Hh, Hl, O_OP, Q, BT, DD, DD, 0, nullptr, 1, 0,0,0,0, 2);
    rms_kernel<<<BT, 256>>>(Q, fnorm, Hh, Hl, DD, BT, 0);
    hgemm(Hh, nullptr, O_EMB, out, BT, BV, DD, 0, nullptr, 1, 0,0,0,0, 1);
}